// round 2
// baseline (speedup 1.0000x reference)
#include <cuda_runtime.h>
#include <cuda_bf16.h>
#include <math.h>

#define VOL   262144   // 64^3
#define NB    2
#define NL    3
#define NF    6        // NB*NL
#define BIGF  1e10f
#define W_ANI 0.096f

// Scratch: distance fields for 6 (batch,label) combos. 6*64^3 floats = 6.29 MB.
__device__ float  g_field[NF * VOL];
__device__ double g_acc;

// ---------------------------------------------------------------------------
// Unified min-plus pass kernel.
// One block = one 64x64 tile (64 lines x 64 elements) of one field.
// Tile addressing: elem(i,c) at  f*VOL + t*tileStride + i*strideI + c*strideC
//   z-pass: tileStride=64   strideI=4096 strideC=1   (tiles over y, i=z, c=x)
//   y-pass: tileStride=4096 strideI=64   strideC=1   (tiles over z, i=y, c=x)
//   x-pass: tileStride=4096 strideI=1    strideC=64  (tiles over z, i=x, c=y)
// First pass fuses initialization from labels (field = lab==L ? 0 : BIG).
//
// min-plus identity used:
//   min_j (f_j + (wi - wj)^2) = wi^2 + min_j ( (f_j + wj^2) - 2*wi*wj )
// with wi = W*i, wj = W*j. Inner candidate: one FFMA (fma pipe) + one
// FMNMX (alu pipe) -> dual-issue.
// ---------------------------------------------------------------------------
__global__ void __launch_bounds__(256)
k_pass(const int* __restrict__ labels,
       int tileStride, int strideI, int strideC, int firstPass)
{
    __shared__ float sh[64 * 65];   // pitch 65 -> conflict-free both orientations

    const int tid = threadIdx.x;
    const int f   = blockIdx.x >> 6;     // field index: b*3 + L
    const int t   = blockIdx.x & 63;     // tile index within field
    const int b   = f / NL;
    const int L   = f - b * NL;
    const int base    = f * VOL + t * tileStride;
    const int labBase = b * VOL + t * tileStride;
    const bool iContig = (strideI == 1);

    // ---- load tile (coalesced: contiguous global axis mapped to tid low bits)
    #pragma unroll
    for (int e = 0; e < 16; ++e) {
        int idx = e * 256 + tid;
        int i, c;
        if (iContig) { i = idx & 63; c = idx >> 6; }
        else         { c = idx & 63; i = idx >> 6; }
        int off = i * strideI + c * strideC;
        float v;
        if (firstPass) v = (labels[labBase + off] == L) ? 0.0f : BIGF;
        else           v = g_field[base + off];
        sh[i * 65 + c] = v;
    }
    __syncthreads();

    // ---- compute: thread (c = tid&63, ig = tid>>6) does outputs i = ig*16..+15
    const int   c  = tid & 63;
    const int   ig = tid >> 6;
    const int   i0 = ig * 16;

    float acc[16];
    float bk[16];   // -2*wi
    float ak[16];   // wi^2
    #pragma unroll
    for (int k = 0; k < 16; ++k) {
        float wi = W_ANI * (float)(i0 + k);
        ak[k]  = wi * wi;
        bk[k]  = -2.0f * wi;          // FIXED: was -2*W*wi (extra factor W)
        acc[k] = 3.0e38f;
    }

    #pragma unroll 4
    for (int j = 0; j < 64; ++j) {
        float wj = W_ANI * (float)j;
        float vj = fmaf(wj, wj, sh[j * 65 + c]);   // f_j + wj^2
        #pragma unroll
        for (int k = 0; k < 16; ++k) {
            acc[k] = fminf(acc[k], fmaf(bk[k], wj, vj));  // + (-2*wi*wj)
        }
    }
    __syncthreads();

    // ---- stage results in shared, then coalesced writeback
    #pragma unroll
    for (int k = 0; k < 16; ++k)
        sh[(i0 + k) * 65 + c] = acc[k] + ak[k];
    __syncthreads();

    #pragma unroll
    for (int e = 0; e < 16; ++e) {
        int idx = e * 256 + tid;
        int i, cc;
        if (iContig) { i = idx & 63; cc = idx >> 6; }
        else         { cc = idx & 63; i = idx >> 6; }
        g_field[base + i * strideI + cc * strideC] = sh[i * 65 + cc];
    }
}

// ---------------------------------------------------------------------------
// Final reduction:
//  d2(b,v)  = min over L != label of field[b,L,v]
//  dt       = sqrt(d2) + 1
//  contrib  = dt * sum_{c=1,2} ( label==c ? (1-x) : x )
//  result   = sum(contrib) / (2*2*64^3) + 1e-5
// ---------------------------------------------------------------------------
__global__ void __launch_bounds__(256)
k_reduce(const float* __restrict__ x, const int* __restrict__ y)
{
    const int stride = blockDim.x * gridDim.x;
    float local = 0.0f;
    for (int idx = blockIdx.x * blockDim.x + threadIdx.x;
         idx < NB * VOL; idx += stride) {
        int b   = idx >> 18;          // /VOL
        int v   = idx & (VOL - 1);
        int lab = y[idx];

        float d2 = 3.0e38f;
        #pragma unroll
        for (int L = 0; L < NL; ++L) {
            float val = g_field[(b * NL + L) * VOL + v];
            if (L != lab) d2 = fminf(d2, val);
        }
        float dt = sqrtf(d2) + 1.0f;

        float s = 0.0f;
        #pragma unroll
        for (int ch = 1; ch < NL; ++ch) {
            float xv = x[(b * NL + ch) * VOL + v];
            s += (lab == ch) ? (1.0f - xv) : xv;
        }
        local += s * dt;
    }

    // warp reduce
    #pragma unroll
    for (int o = 16; o; o >>= 1)
        local += __shfl_xor_sync(0xFFFFFFFFu, local, o);

    __shared__ float wsum[8];
    int lane = threadIdx.x & 31;
    int w    = threadIdx.x >> 5;
    if (lane == 0) wsum[w] = local;
    __syncthreads();
    if (threadIdx.x == 0) {
        float s = 0.0f;
        #pragma unroll
        for (int i = 0; i < 8; ++i) s += wsum[i];
        atomicAdd(&g_acc, (double)s);
    }
}

__global__ void k_zero() { g_acc = 0.0; }

__global__ void k_final(float* __restrict__ out)
{
    // mean(fp) + mean(fn) over (2 batches, 2 channels, 64^3) each
    const double inv = 1.0 / (double)(NB * 2 * VOL);
    out[0] = (float)(g_acc * inv + 1e-5);
}

// ---------------------------------------------------------------------------
extern "C" void kernel_launch(void* const* d_in, const int* in_sizes, int n_in,
                              void* d_out, int out_size)
{
    const float* x = (const float*)d_in[0];   // (2,3,64,64,64) float32
    const int*   y = (const int*)  d_in[1];   // (2,1,64,64,64) int32
    float* out = (float*)d_out;

    k_zero<<<1, 1>>>();
    // Fused init + z-pass, then y-pass, then x-pass (min-plus passes commute).
    k_pass<<<NF * 64, 256>>>(y,   64, 4096,  1, 1);  // z
    k_pass<<<NF * 64, 256>>>(y, 4096,   64,  1, 0);  // y
    k_pass<<<NF * 64, 256>>>(y, 4096,    1, 64, 0);  // x
    k_reduce<<<1024, 256>>>(x, y);
    k_final<<<1, 1>>>(out);
}

// round 3
// speedup vs baseline: 1.2181x; 1.2181x over previous
#include <cuda_runtime.h>
#include <math.h>

#define VOL   262144    // 64^3
#define HVOL  131072    // VOL/2 (u32 words of packed u16 pairs)
#define NB    2
#define NL    3
#define NF    6
#define INF16 25000     // integer "infinity"; INF16 + 63^2 < 32767 (no s16 overflow)
#define W_ANI 0.096f

// Fields as u16 squared-distance (integer voxel units). 6 * 64^3 * 2B = 3 MB.
__device__ unsigned g_field32[NF * HVOL];
__device__ double   g_acc;

// ---------------------------------------------------------------------------
// Unified integer min-plus pass:  out(i,line) = min_j ( n(j,line) + (i-j)^2 )
// computed exactly in s16, two lines packed per 32-bit lane (VIADDMNMX).
//
// MODE 0 (z-pass): block=(field f, y=t). line axis = x, scan axis j = z.
//                  input = labels (init fused), output u16 field (z,y,x).
// MODE 1 (y-pass): block=(f, z=t). line = x, j = y. in-place on field plane.
// MODE 2 (x-pass): block=(f, z=t). line = y, j = x. shared transpose on both
//                  load and store to keep global accesses coalesced.
//
// Thread org (compute): cp = tid&31 -> lines {2cp, 2cp+1}; og = tid>>5 ->
// outputs i0=og*8 .. i0+7. Warp-uniform og => delta^2 LUT loads broadcast.
// LUT holds dup16(d^2) in 4 shift-copies so &lut[135*(B&3)+B] is 16B-aligned
// (135*s + B ≡ 136*s ≡ 0 mod 4 when B≡s mod 4) -> two LDS.128 per j.
// ---------------------------------------------------------------------------
template<int MODE>
__global__ void __launch_bounds__(256)
k_pass(const int* __restrict__ labels)
{
    __shared__ unsigned sh_v[64 * 33];     // [j][cp] packed pair, pitch 33 words
    __shared__ unsigned sh_lut[536];       // 4 shifted copies of dup(d^2), d in [-63,63]
    unsigned short* sh16 = (unsigned short*)sh_v;   // u16 view: [j*66 + line]

    const int tid = threadIdx.x;
    const int f   = blockIdx.x >> 6;
    const int t   = blockIdx.x & 63;

    // ---- build delta^2 LUT (127 entries x 4 copies)
    if (tid < 127) {
        int d = tid - 63;
        unsigned q = (unsigned)(d * d) * 0x10001u;
        #pragma unroll
        for (int s = 0; s < 4; ++s) sh_lut[135 * s + tid] = q;
    }

    // ---- load tile into sh_v (all global traffic coalesced)
    if (MODE == 0) {
        const int b = f / NL, L = f - b * NL;
        const int2* lab2 = (const int2*)labels;
        #pragma unroll
        for (int e = 0; e < 8; ++e) {
            int idx = e * 256 + tid;
            int j = idx >> 5, c2 = idx & 31;
            int2 lv = lab2[b * HVOL + j * 2048 + t * 32 + c2];
            unsigned n0 = (lv.x == L) ? 0u : (unsigned)INF16;
            unsigned n1 = (lv.y == L) ? 0u : (unsigned)INF16;
            sh_v[j * 33 + c2] = n0 | (n1 << 16);
        }
    } else if (MODE == 1) {
        #pragma unroll
        for (int e = 0; e < 8; ++e) {
            int idx = e * 256 + tid;
            int j = idx >> 5, c2 = idx & 31;
            sh_v[j * 33 + c2] = g_field32[f * HVOL + t * 2048 + j * 32 + c2];
        }
    } else { // MODE 2: transpose on load: word covers (y, x=2xp..2xp+1)
        #pragma unroll
        for (int e = 0; e < 8; ++e) {
            int idx = e * 256 + tid;
            int y = idx >> 5, xp = idx & 31;
            unsigned w = g_field32[f * HVOL + t * 2048 + idx];
            sh16[(2 * xp) * 66 + y]     = (unsigned short)(w & 0xFFFFu);
            sh16[(2 * xp + 1) * 66 + y] = (unsigned short)(w >> 16);
        }
    }
    __syncthreads();

    // ---- compute
    const int cp = tid & 31;
    const int i0 = (tid >> 5) * 8;

    unsigned acc[8];
    #pragma unroll
    for (int k = 0; k < 8; ++k) acc[k] = 0x7FFF7FFFu;

    #pragma unroll 8
    for (int j = 0; j < 64; ++j) {
        unsigned vj = sh_v[j * 33 + cp];
        int B = i0 + 63 - j;                       // LUT index for k=0
        const unsigned* lp = &sh_lut[135 * (B & 3) + B];   // 16B-aligned
        uint4 q0 = *(const uint4*)(lp);
        uint4 q1 = *(const uint4*)(lp + 4);
        acc[0] = __viaddmin_s16x2(vj, q0.x, acc[0]);
        acc[1] = __viaddmin_s16x2(vj, q0.y, acc[1]);
        acc[2] = __viaddmin_s16x2(vj, q0.z, acc[2]);
        acc[3] = __viaddmin_s16x2(vj, q0.w, acc[3]);
        acc[4] = __viaddmin_s16x2(vj, q1.x, acc[4]);
        acc[5] = __viaddmin_s16x2(vj, q1.y, acc[5]);
        acc[6] = __viaddmin_s16x2(vj, q1.z, acc[6]);
        acc[7] = __viaddmin_s16x2(vj, q1.w, acc[7]);
    }

    const unsigned infDup = ((unsigned)INF16 << 16) | (unsigned)INF16;
    #pragma unroll
    for (int k = 0; k < 8; ++k) acc[k] = __vminu2(acc[k], infDup);

    // ---- writeback
    if (MODE == 0) {
        int base = f * HVOL + t * 32 + cp;        // u32 word (z=i, y=t, x=2cp)
        #pragma unroll
        for (int k = 0; k < 8; ++k)
            g_field32[base + (i0 + k) * 2048] = acc[k];
    } else if (MODE == 1) {
        int base = f * HVOL + t * 2048 + cp;      // (z=t, y=i, x=2cp)
        #pragma unroll
        for (int k = 0; k < 8; ++k)
            g_field32[base + (i0 + k) * 32] = acc[k];
    } else { // MODE 2: stage transposed, then coalesced store
        __syncthreads();
        #pragma unroll
        for (int k = 0; k < 8; ++k)
            sh_v[(i0 + k) * 33 + cp] = acc[k];    // sh16[x*66 + line(y)]
        __syncthreads();
        #pragma unroll
        for (int e = 0; e < 8; ++e) {
            int idx = e * 256 + tid;
            int y = idx >> 5, xp = idx & 31;
            unsigned lo = sh16[(2 * xp) * 66 + y];
            unsigned hi = sh16[(2 * xp + 1) * 66 + y];
            g_field32[f * HVOL + t * 2048 + idx] = lo | (hi << 16);
        }
    }
}

// ---------------------------------------------------------------------------
// Reduce: per voxel, m = min over L != lab of n_L ; dt = w*sqrt(m) + 1 ;
// contrib = dt * sum_{ch=1,2} ( lab==ch ? 1-x : x ). Two voxels per iteration.
// ---------------------------------------------------------------------------
__global__ void __launch_bounds__(256)
k_reduce(const float* __restrict__ x, const int* __restrict__ y)
{
    const int stride = blockDim.x * gridDim.x;
    float local = 0.0f;
    for (int p = blockIdx.x * blockDim.x + threadIdx.x;
         p < NB * HVOL; p += stride) {
        int b = p >> 17;                 // / HVOL
        int v = p & (HVOL - 1);
        unsigned f0 = g_field32[(b * 3 + 0) * HVOL + v];
        unsigned f1 = g_field32[(b * 3 + 1) * HVOL + v];
        unsigned f2 = g_field32[(b * 3 + 2) * HVOL + v];
        int2   yy = ((const int2*)y)[p];
        float2 x1 = ((const float2*)x)[(b * 3 + 1) * HVOL + v];
        float2 x2 = ((const float2*)x)[(b * 3 + 2) * HVOL + v];

        {   // voxel 0 (low halves)
            int lab = yy.x;
            int n0 = (int)(f0 & 0xFFFFu), n1 = (int)(f1 & 0xFFFFu), n2 = (int)(f2 & 0xFFFFu);
            int m = min(lab == 0 ? 0x7FFF : n0,
                    min(lab == 1 ? 0x7FFF : n1,
                        lab == 2 ? 0x7FFF : n2));
            float dt = fmaf(W_ANI, sqrtf((float)m), 1.0f);
            float s  = ((lab == 1) ? (1.0f - x1.x) : x1.x)
                     + ((lab == 2) ? (1.0f - x2.x) : x2.x);
            local += s * dt;
        }
        {   // voxel 1 (high halves)
            int lab = yy.y;
            int n0 = (int)(f0 >> 16), n1 = (int)(f1 >> 16), n2 = (int)(f2 >> 16);
            int m = min(lab == 0 ? 0x7FFF : n0,
                    min(lab == 1 ? 0x7FFF : n1,
                        lab == 2 ? 0x7FFF : n2));
            float dt = fmaf(W_ANI, sqrtf((float)m), 1.0f);
            float s  = ((lab == 1) ? (1.0f - x1.y) : x1.y)
                     + ((lab == 2) ? (1.0f - x2.y) : x2.y);
            local += s * dt;
        }
    }

    #pragma unroll
    for (int o = 16; o; o >>= 1)
        local += __shfl_xor_sync(0xFFFFFFFFu, local, o);

    __shared__ float wsum[8];
    int lane = threadIdx.x & 31, w = threadIdx.x >> 5;
    if (lane == 0) wsum[w] = local;
    __syncthreads();
    if (threadIdx.x == 0) {
        float s = 0.0f;
        #pragma unroll
        for (int i = 0; i < 8; ++i) s += wsum[i];
        atomicAdd(&g_acc, (double)s);
    }
}

__global__ void k_zero() { g_acc = 0.0; }

__global__ void k_final(float* __restrict__ out)
{
    const double inv = 1.0 / (double)(NB * 2 * VOL);
    out[0] = (float)(g_acc * inv + 1e-5);
}

// ---------------------------------------------------------------------------
extern "C" void kernel_launch(void* const* d_in, const int* in_sizes, int n_in,
                              void* d_out, int out_size)
{
    const float* x = (const float*)d_in[0];   // (2,3,64,64,64) f32
    const int*   y = (const int*)  d_in[1];   // (2,1,64,64,64) i32
    float* out = (float*)d_out;

    k_zero<<<1, 1>>>();
    k_pass<0><<<NF * 64, 256>>>(y);   // z-pass (init fused)
    k_pass<1><<<NF * 64, 256>>>(y);   // y-pass
    k_pass<2><<<NF * 64, 256>>>(y);   // x-pass
    k_reduce<<<256, 256>>>(x, y);
    k_final<<<1, 1>>>(out);
}

// round 4
// speedup vs baseline: 1.9560x; 1.6058x over previous
#include <cuda_runtime.h>
#include <math.h>

#define VOL   262144    // 64^3
#define HVOL  131072    // u32 words of packed u16 pairs
#define NB    2
#define NL    3
#define NF    6
#define INF16 25000     // clamp value; INF16 + 63^2 = 28969 < 32767 (s16 safe)
#define W_ANI 0.096f

// Fields as u16 squared-distance (integer voxel units). 6 * 64^3 * 2B = 3 MB.
__device__ unsigned g_field32[NF * HVOL];
__device__ double   g_acc;

// ---------------------------------------------------------------------------
// Pass Z: binary-input 1D squared EDT along z via 64-bit masks.
// Block = (batch b, y). Threads: x = tid&63, seg = tid>>6 (z-quarter).
// Each thread loads 16 z's of labels (coalesced), builds per-label partial
// masks, combines via shared, then computes d^2 = (dist to nearest set bit)^2
// for its 16 z outputs, all 3 labels. Also zeroes g_acc (block 0).
// ---------------------------------------------------------------------------
__global__ void __launch_bounds__(256)
k_passz(const int* __restrict__ labels)
{
    __shared__ unsigned short smk[3 * 4 * 64];

    const int tid = threadIdx.x;
    const int b   = (int)blockIdx.x >> 6;
    const int y   = (int)blockIdx.x & 63;
    const int x   = tid & 63;
    const int seg = tid >> 6;

    if (blockIdx.x == 0 && tid == 0) g_acc = 0.0;

    // build partial masks for z in [16*seg, 16*seg+16)
    unsigned m0 = 0, m1 = 0, m2 = 0;
    const int* lp = labels + b * VOL + (seg * 16) * 4096 + y * 64 + x;
    #pragma unroll
    for (int zz = 0; zz < 16; ++zz) {
        int lab = lp[zz * 4096];
        m0 |= (lab == 0) ? (1u << zz) : 0u;
        m1 |= (lab == 1) ? (1u << zz) : 0u;
        m2 |= (lab == 2) ? (1u << zz) : 0u;
    }
    smk[(0 * 4 + seg) * 64 + x] = (unsigned short)m0;
    smk[(1 * 4 + seg) * 64 + x] = (unsigned short)m1;
    smk[(2 * 4 + seg) * 64 + x] = (unsigned short)m2;
    __syncthreads();

    unsigned short* g16 = (unsigned short*)g_field32;

    #pragma unroll
    for (int L = 0; L < NL; ++L) {
        unsigned long long m =
              (unsigned long long)smk[(L * 4 + 0) * 64 + x]
            | ((unsigned long long)smk[(L * 4 + 1) * 64 + x] << 16)
            | ((unsigned long long)smk[(L * 4 + 2) * 64 + x] << 32)
            | ((unsigned long long)smk[(L * 4 + 3) * 64 + x] << 48);
        const int fbase = (b * NL + L) * VOL + y * 64 + x;
        #pragma unroll
        for (int kk = 0; kk < 16; ++kk) {
            int i = seg * 16 + kk;
            unsigned long long below = m & (~0ULL >> (63 - i));
            unsigned long long above = m >> i;
            int dp = below ? (i - (63 - __clzll(below))) : 1000;
            int dn = above ? (__ffsll(above) - 1)        : 1000;
            int d  = min(dp, dn);
            int d2 = (d > 63) ? INF16 : d * d;
            g16[fbase + i * 4096] = (unsigned short)d2;
        }
    }
}

// ---------------------------------------------------------------------------
// Sliding-window SIMD min-plus over one 64x64 plane held in shared.
// sbuf layout: word [j*33 + cp] = packed pair (line 2cp, 2cp+1) at scan pos j.
// Thread: cp = tid&31 (line pair), i0 = (tid>>5)*8 (8 outputs).
// lut[idx] = dup16((idx-63)^2), idx 0..126, lut[127]=pad.
// Per 4 j's: 3 aligned LDS.128 give the 11-word delta^2 window; each sub-j
// statically selects its 8-word slice. 32 VIADDMNMX per group.
// ---------------------------------------------------------------------------
__device__ __forceinline__ void minplus64(const unsigned* __restrict__ sbuf,
                                          const unsigned* __restrict__ lut,
                                          int cp, int i0, unsigned acc[8])
{
    #pragma unroll
    for (int k = 0; k < 8; ++k) acc[k] = 0x7FFF7FFFu;

    #pragma unroll 4
    for (int g = 0; g < 16; ++g) {
        const int s = i0 + 60 - 4 * g;                 // i0 % 4 == 0 -> aligned
        const uint4 qa = *(const uint4*)(lut + s);
        const uint4 qb = *(const uint4*)(lut + s + 4);
        const uint4 qc = *(const uint4*)(lut + s + 8);
        unsigned q[12] = { qa.x, qa.y, qa.z, qa.w,
                           qb.x, qb.y, qb.z, qb.w,
                           qc.x, qc.y, qc.z, qc.w };
        #pragma unroll
        for (int r = 0; r < 4; ++r) {
            unsigned vj = sbuf[(4 * g + r) * 33 + cp];
            #pragma unroll
            for (int k = 0; k < 8; ++k)
                acc[k] = __viaddmin_s16x2(vj, q[3 - r + k], acc[k]);
        }
    }
}

// ---------------------------------------------------------------------------
// Fused Y+X pass. Block = (field f, z = t). Plane stays in shared:
// load (coalesced) -> min-plus along y -> clamp -> transpose (u16) ->
// min-plus along x -> transpose back -> store (coalesced).
// ---------------------------------------------------------------------------
__global__ void __launch_bounds__(256)
k_passyx()
{
    __shared__ unsigned sv[64 * 33];
    __shared__ unsigned sw[64 * 33];
    __shared__ unsigned lut[128];

    const int tid = threadIdx.x;
    const int f   = (int)blockIdx.x >> 6;
    const int t   = (int)blockIdx.x & 63;
    const unsigned base = f * HVOL + t * 2048;

    if (tid < 128) {
        int d = tid - 63;
        lut[tid] = (tid < 127) ? (unsigned)(d * d) * 0x10001u : 0u;
    }
    #pragma unroll
    for (int e = 0; e < 8; ++e) {
        int idx = e * 256 + tid;
        sv[(idx >> 5) * 33 + (idx & 31)] = g_field32[base + idx];
    }
    __syncthreads();

    const int cp = tid & 31;
    const int i0 = (tid >> 5) * 8;
    unsigned acc[8];

    // ---- y-pass (j = y, packed pairs along x)
    minplus64(sv, lut, cp, i0, acc);
    const unsigned infDup = ((unsigned)INF16 << 16) | (unsigned)INF16;
    unsigned short* sw16 = (unsigned short*)sw;
    #pragma unroll
    for (int k = 0; k < 8; ++k) {
        unsigned a = __vminu2(acc[k], infDup);         // clamp before next add
        sw16[(2 * cp)     * 66 + (i0 + k)] = (unsigned short)(a & 0xFFFFu);
        sw16[(2 * cp + 1) * 66 + (i0 + k)] = (unsigned short)(a >> 16);
    }
    __syncthreads();

    // ---- x-pass (j = x, packed pairs along y); sw word [x*33 + ypair]
    minplus64(sw, lut, cp, i0, acc);
    unsigned short* sv16 = (unsigned short*)sv;
    #pragma unroll
    for (int k = 0; k < 8; ++k) {                      // result (y=2cp(+1), x=i0+k)
        sv16[(2 * cp)     * 66 + (i0 + k)] = (unsigned short)(acc[k] & 0xFFFFu);
        sv16[(2 * cp + 1) * 66 + (i0 + k)] = (unsigned short)(acc[k] >> 16);
    }
    __syncthreads();

    #pragma unroll
    for (int e = 0; e < 8; ++e) {
        int idx = e * 256 + tid;
        g_field32[base + idx] = sv[(idx >> 5) * 33 + (idx & 31)];
    }
}

// ---------------------------------------------------------------------------
// Reduce: per voxel, m = min over L != lab of n_L ; dt = w*sqrt(m) + 1 ;
// contrib = dt * sum_{ch=1,2} ( lab==ch ? 1-x : x ). Two voxels per word.
// ---------------------------------------------------------------------------
__global__ void __launch_bounds__(256)
k_reduce(const float* __restrict__ x, const int* __restrict__ y)
{
    const int stride = blockDim.x * gridDim.x;
    float local = 0.0f;
    for (int p = blockIdx.x * blockDim.x + threadIdx.x;
         p < NB * HVOL; p += stride) {
        int b = p >> 17;
        int v = p & (HVOL - 1);
        unsigned f0 = g_field32[(b * 3 + 0) * HVOL + v];
        unsigned f1 = g_field32[(b * 3 + 1) * HVOL + v];
        unsigned f2 = g_field32[(b * 3 + 2) * HVOL + v];
        int2   yy = ((const int2*)y)[p];
        float2 x1 = ((const float2*)x)[(b * 3 + 1) * HVOL + v];
        float2 x2 = ((const float2*)x)[(b * 3 + 2) * HVOL + v];

        {
            int lab = yy.x;
            int n0 = (int)(f0 & 0xFFFFu), n1 = (int)(f1 & 0xFFFFu), n2 = (int)(f2 & 0xFFFFu);
            int m = min(lab == 0 ? 0x7FFF : n0,
                    min(lab == 1 ? 0x7FFF : n1,
                        lab == 2 ? 0x7FFF : n2));
            float dt = fmaf(W_ANI, sqrtf((float)m), 1.0f);
            float s  = ((lab == 1) ? (1.0f - x1.x) : x1.x)
                     + ((lab == 2) ? (1.0f - x2.x) : x2.x);
            local += s * dt;
        }
        {
            int lab = yy.y;
            int n0 = (int)(f0 >> 16), n1 = (int)(f1 >> 16), n2 = (int)(f2 >> 16);
            int m = min(lab == 0 ? 0x7FFF : n0,
                    min(lab == 1 ? 0x7FFF : n1,
                        lab == 2 ? 0x7FFF : n2));
            float dt = fmaf(W_ANI, sqrtf((float)m), 1.0f);
            float s  = ((lab == 1) ? (1.0f - x1.y) : x1.y)
                     + ((lab == 2) ? (1.0f - x2.y) : x2.y);
            local += s * dt;
        }
    }

    #pragma unroll
    for (int o = 16; o; o >>= 1)
        local += __shfl_xor_sync(0xFFFFFFFFu, local, o);

    __shared__ float wsum[8];
    int lane = threadIdx.x & 31, w = threadIdx.x >> 5;
    if (lane == 0) wsum[w] = local;
    __syncthreads();
    if (threadIdx.x == 0) {
        float s = 0.0f;
        #pragma unroll
        for (int i = 0; i < 8; ++i) s += wsum[i];
        atomicAdd(&g_acc, (double)s);
    }
}

__global__ void k_final(float* __restrict__ out)
{
    const double inv = 1.0 / (double)(NB * 2 * VOL);
    out[0] = (float)(g_acc * inv + 1e-5);
}

// ---------------------------------------------------------------------------
extern "C" void kernel_launch(void* const* d_in, const int* in_sizes, int n_in,
                              void* d_out, int out_size)
{
    const float* x = (const float*)d_in[0];   // (2,3,64,64,64) f32
    const int*   y = (const int*)  d_in[1];   // (2,1,64,64,64) i32
    float* out = (float*)d_out;

    k_passz <<<NB * 64, 256>>>(y);     // z-pass via bitmasks (+ g_acc zero)
    k_passyx<<<NF * 64, 256>>>();      // fused y-pass + x-pass in shared
    k_reduce<<<256, 256>>>(x, y);
    k_final <<<1, 1>>>(out);
}

// round 5
// speedup vs baseline: 1.9778x; 1.0111x over previous
#include <cuda_runtime.h>
#include <math.h>

#define VOL   262144    // 64^3
#define NB    2
#define NL    3
#define INF16 25000     // clamp; INF16 + 63^2 = 28969 < 32767 (s16-safe)
#define W_ANI 0.096f

// Per-column z occupancy masks: g_mask[(b*3+L)*4096 + y*64 + x] bit z = (label==L)
__device__ unsigned long long g_mask[NB * NL * 4096];   // 192 KB
__device__ double   g_acc;     // zero-init; reset by finalizer each run
__device__ unsigned g_done;    // zero-init; reset by finalizer each run

// ---------------------------------------------------------------------------
// Kernel A: build z-masks. Block = (b, y). 2 MB coalesced label read.
// ---------------------------------------------------------------------------
__global__ void __launch_bounds__(256)
k_masks(const int* __restrict__ labels)
{
    __shared__ unsigned short smk[NL * 4 * 64];
    const int tid = threadIdx.x;
    const int b = (int)blockIdx.x >> 6, y = (int)blockIdx.x & 63;
    const int x = tid & 63, seg = tid >> 6;

    unsigned m0 = 0, m1 = 0, m2 = 0;
    const int* lp = labels + b * VOL + seg * 16 * 4096 + y * 64 + x;
    #pragma unroll
    for (int zz = 0; zz < 16; ++zz) {
        int lab = lp[zz * 4096];
        m0 |= (lab == 0) ? (1u << zz) : 0u;
        m1 |= (lab == 1) ? (1u << zz) : 0u;
        m2 |= (lab == 2) ? (1u << zz) : 0u;
    }
    smk[(0 * 4 + seg) * 64 + x] = (unsigned short)m0;
    smk[(1 * 4 + seg) * 64 + x] = (unsigned short)m1;
    smk[(2 * 4 + seg) * 64 + x] = (unsigned short)m2;
    __syncthreads();

    if (tid < 192) {
        int L = tid >> 6, xx = tid & 63;
        unsigned long long m =
              (unsigned long long)smk[(L * 4 + 0) * 64 + xx]
            | ((unsigned long long)smk[(L * 4 + 1) * 64 + xx] << 16)
            | ((unsigned long long)smk[(L * 4 + 2) * 64 + xx] << 32)
            | ((unsigned long long)smk[(L * 4 + 3) * 64 + xx] << 48);
        g_mask[(b * NL + L) * 4096 + y * 64 + xx] = m;
    }
}

// ---------------------------------------------------------------------------
// SIMD min-plus along one axis of a 64x64 plane in shared.
// sbuf word [j*33 + cp] = packed pair (line 2cp, 2cp+1) at scan pos j.
// Thread: cp = tid&31 (line pair), i0 = (tid>>5)*4 (4 outputs).
// Per 4 j's: 2 aligned LDS.128 of the dup16 delta^2 window + 16 VIADDMNMX.
// ---------------------------------------------------------------------------
__device__ __forceinline__ void minplus4(const unsigned* __restrict__ sbuf,
                                         const unsigned* __restrict__ lut,
                                         int cp, int i0, unsigned acc[4])
{
    #pragma unroll
    for (int k = 0; k < 4; ++k) acc[k] = 0x7FFF7FFFu;

    #pragma unroll 4
    for (int g = 0; g < 16; ++g) {
        const int s = i0 + 60 - 4 * g;                 // %4 == 0 -> aligned
        const uint4 qa = *(const uint4*)(lut + s);
        const uint4 qb = *(const uint4*)(lut + s + 4);
        unsigned q[8] = { qa.x, qa.y, qa.z, qa.w, qb.x, qb.y, qb.z, qb.w };
        #pragma unroll
        for (int r = 0; r < 4; ++r) {
            unsigned vj = sbuf[(4 * g + r) * 33 + cp];
            #pragma unroll
            for (int k = 0; k < 4; ++k)
                acc[k] = __viaddmin_s16x2(vj, q[3 - r + k], acc[k]);
        }
    }
}

// ---------------------------------------------------------------------------
// Kernel B: everything else. Block = (b, z-plane t), 128 blocks, 512 threads.
// Per label: z-distance from masks -> y-minplus -> x-minplus -> res[L] (shared).
// Then fused masked-min reduce over the plane + last-block finalize.
// ---------------------------------------------------------------------------
__global__ void __launch_bounds__(512, 1)
k_main(const float* __restrict__ x, const int* __restrict__ y,
       float* __restrict__ out)
{
    __shared__ unsigned lut[128];
    __shared__ unsigned sv[64 * 33];
    __shared__ unsigned sw[64 * 33];
    __shared__ unsigned short res[NL][64 * 66];
    __shared__ float wsum[16];

    const int tid = threadIdx.x;
    const int b = (int)blockIdx.x >> 6, t = (int)blockIdx.x & 63;
    const int cp = tid & 31;
    const int i0 = (tid >> 5) * 4;

    if (tid < 128) {
        int d = tid - 63;
        lut[tid] = (tid < 127) ? (unsigned)(d * d) * 0x10001u : 0u;
    }

    const unsigned long long keep = ~0ULL >> (63 - t);
    unsigned short* sw16 = (unsigned short*)sw;
    const unsigned infDup = ((unsigned)INF16 << 16) | (unsigned)INF16;

    for (int L = 0; L < NL; ++L) {
        // ---- z-pass value at plane t, straight from masks
        const uint4* mp = (const uint4*)&g_mask[(b * NL + L) * 4096];
        #pragma unroll
        for (int e = 0; e < 4; ++e) {
            int widx = e * 512 + tid;         // 2048 packed words
            int yy = widx >> 5, xp = widx & 31;
            uint4 mm = mp[yy * 32 + xp];      // two u64 (x = 2xp, 2xp+1)
            unsigned long long ma = ((unsigned long long)mm.y << 32) | mm.x;
            unsigned long long mb = ((unsigned long long)mm.w << 32) | mm.z;
            unsigned d2a, d2b;
            {
                unsigned long long bl = ma & keep, ab = ma >> t;
                int dp = bl ? (t - (63 - __clzll((long long)bl))) : 999;
                int dn = ab ? (__ffsll((long long)ab) - 1) : 999;
                int d = min(dp, dn);
                d2a = (d > 63) ? (unsigned)INF16 : (unsigned)(d * d);
            }
            {
                unsigned long long bl = mb & keep, ab = mb >> t;
                int dp = bl ? (t - (63 - __clzll((long long)bl))) : 999;
                int dn = ab ? (__ffsll((long long)ab) - 1) : 999;
                int d = min(dp, dn);
                d2b = (d > 63) ? (unsigned)INF16 : (unsigned)(d * d);
            }
            sv[yy * 33 + xp] = d2a | (d2b << 16);
        }
        __syncthreads();

        unsigned acc[4];
        // ---- y-minplus (lines = x), clamp, transpose into sw
        minplus4(sv, lut, cp, i0, acc);
        #pragma unroll
        for (int k = 0; k < 4; ++k) {
            unsigned a = __vminu2(acc[k], infDup);
            sw16[(2 * cp)     * 66 + i0 + k] = (unsigned short)(a & 0xFFFFu);
            sw16[(2 * cp + 1) * 66 + i0 + k] = (unsigned short)(a >> 16);
        }
        __syncthreads();

        // ---- x-minplus (lines = y) -> res[L][y*66 + x]
        minplus4(sw, lut, cp, i0, acc);
        #pragma unroll
        for (int k = 0; k < 4; ++k) {
            res[L][(2 * cp)     * 66 + i0 + k] = (unsigned short)(acc[k] & 0xFFFFu);
            res[L][(2 * cp + 1) * 66 + i0 + k] = (unsigned short)(acc[k] >> 16);
        }
        __syncthreads();
    }

    // ---- fused reduce over this plane (all loads coalesced)
    float local = 0.0f;
    const int pbase = b * VOL + t * 4096;
    #pragma unroll
    for (int e = 0; e < 8; ++e) {
        int v  = e * 512 + tid;
        int lab = y[pbase + v];
        int yy = v >> 6, xx = v & 63;
        int n0 = res[0][yy * 66 + xx];
        int n1 = res[1][yy * 66 + xx];
        int n2 = res[2][yy * 66 + xx];
        int m = min(lab == 0 ? 0x7FFF : n0,
                min(lab == 1 ? 0x7FFF : n1,
                    lab == 2 ? 0x7FFF : n2));
        float dt = fmaf(W_ANI, sqrtf((float)m), 1.0f);
        float x1 = x[(b * NL + 1) * VOL + t * 4096 + v];
        float x2 = x[(b * NL + 2) * VOL + t * 4096 + v];
        float s  = ((lab == 1) ? (1.0f - x1) : x1)
                 + ((lab == 2) ? (1.0f - x2) : x2);
        local += s * dt;
    }

    #pragma unroll
    for (int o = 16; o; o >>= 1)
        local += __shfl_xor_sync(0xFFFFFFFFu, local, o);
    if ((tid & 31) == 0) wsum[tid >> 5] = local;
    __syncthreads();

    if (tid == 0) {
        float s = 0.0f;
        #pragma unroll
        for (int i = 0; i < 16; ++i) s += wsum[i];
        atomicAdd(&g_acc, (double)s);
        __threadfence();
        unsigned old = atomicAdd(&g_done, 1u);
        if (old == gridDim.x - 1) {          // last block: finalize + reset
            double tot = atomicAdd(&g_acc, 0.0);
            out[0] = (float)(tot / (double)(NB * 2 * VOL) + 1e-5);
            g_acc  = 0.0;
            g_done = 0u;
            __threadfence();
        }
    }
}

// ---------------------------------------------------------------------------
extern "C" void kernel_launch(void* const* d_in, const int* in_sizes, int n_in,
                              void* d_out, int out_size)
{
    const float* x = (const float*)d_in[0];   // (2,3,64,64,64) f32
    const int*   y = (const int*)  d_in[1];   // (2,1,64,64,64) i32
    float* out = (float*)d_out;

    k_masks<<<NB * 64, 256>>>(y);
    k_main <<<NB * 64, 512>>>(x, y, out);
}

// round 6
// speedup vs baseline: 2.2390x; 1.1321x over previous
#include <cuda_runtime.h>
#include <math.h>

#define VOL   262144    // 64^3
#define NB    2
#define NL    3
#define INF16 25000     // clamp; INF16 + 63^2 = 28969 < 32767 (s16-safe)
#define W_ANI 0.096f

// Per-column z occupancy masks: g_mask[(b*3+L)*4096 + y*64 + x] bit z = (label==L)
__device__ unsigned long long g_mask[NB * NL * 4096];   // 192 KB
__device__ double   g_acc;     // zero-init; reset by finalizer each run
__device__ unsigned g_done;

// ---------------------------------------------------------------------------
// Kernel A: build z-masks. Block = (b, y). 2 MB coalesced label read.
// ---------------------------------------------------------------------------
__global__ void __launch_bounds__(256)
k_masks(const int* __restrict__ labels)
{
    __shared__ unsigned short smk[NL * 4 * 64];
    const int tid = threadIdx.x;
    const int b = (int)blockIdx.x >> 6, y = (int)blockIdx.x & 63;
    const int x = tid & 63, seg = tid >> 6;

    unsigned m0 = 0, m1 = 0, m2 = 0;
    const int* lp = labels + b * VOL + seg * 16 * 4096 + y * 64 + x;
    #pragma unroll
    for (int zz = 0; zz < 16; ++zz) {
        int lab = lp[zz * 4096];
        m0 |= (lab == 0) ? (1u << zz) : 0u;
        m1 |= (lab == 1) ? (1u << zz) : 0u;
        m2 |= (lab == 2) ? (1u << zz) : 0u;
    }
    smk[(0 * 4 + seg) * 64 + x] = (unsigned short)m0;
    smk[(1 * 4 + seg) * 64 + x] = (unsigned short)m1;
    smk[(2 * 4 + seg) * 64 + x] = (unsigned short)m2;
    __syncthreads();

    if (tid < 192) {
        int L = tid >> 6, xx = tid & 63;
        unsigned long long m =
              (unsigned long long)smk[(L * 4 + 0) * 64 + xx]
            | ((unsigned long long)smk[(L * 4 + 1) * 64 + xx] << 16)
            | ((unsigned long long)smk[(L * 4 + 2) * 64 + xx] << 32)
            | ((unsigned long long)smk[(L * 4 + 3) * 64 + xx] << 48);
        g_mask[(b * NL + L) * 4096 + y * 64 + xx] = m;
    }
}

// ---------------------------------------------------------------------------
// Kernel B: block = (b, z-plane t), 128 blocks x 1024 threads.
// All 3 labels processed together in each phase; the j-dimension of each
// min-plus is split across the two 512-thread halves (partial min + combine).
// Plane pipeline: z-vals (from masks) -> y-minplus -> transpose -> x-minplus
// -> fused masked reduce -> grid-atomic accumulate; last block finalizes.
// ---------------------------------------------------------------------------
__global__ void __launch_bounds__(1024, 1)
k_main(const float* __restrict__ x, const int* __restrict__ y,
       float* __restrict__ out)
{
    __shared__ unsigned lut[128];
    __shared__ unsigned sv[NL][64 * 33];   // input plane / final result (u16 view)
    __shared__ unsigned sw[NL][64 * 33];   // y-pass output, transposed
    __shared__ unsigned scr[NL][2048];     // partial-min exchange
    __shared__ float    wsum[32];

    const int tid = threadIdx.x;
    const int b  = (int)blockIdx.x >> 6, t = (int)blockIdx.x & 63;
    const int cp = tid & 31;
    const int i0 = ((tid >> 5) & 15) * 4;
    const int jh = tid >> 9;                       // j-half: 0 or 1

    if (tid < 128) {
        int d = tid - 63;
        lut[tid] = (tid < 127) ? (unsigned)(d * d) * 0x10001u : 0u;
    }

    // ---- phase 1: z-pass values for all 3 labels, straight from masks
    const unsigned long long keep = ~0ULL >> (63 - t);
    #pragma unroll
    for (int L = 0; L < NL; ++L) {
        const uint4* mp = (const uint4*)&g_mask[(b * NL + L) * 4096];
        #pragma unroll
        for (int e = 0; e < 2; ++e) {
            int widx = e * 1024 + tid;             // 2048 packed words
            int yy = widx >> 5, xp = widx & 31;
            uint4 mm = mp[widx];                    // two u64 (x = 2xp, 2xp+1)
            unsigned long long ma = ((unsigned long long)mm.y << 32) | mm.x;
            unsigned long long mb = ((unsigned long long)mm.w << 32) | mm.z;
            unsigned d2a, d2b;
            {
                unsigned long long bl = ma & keep, ab = ma >> t;
                int dp = bl ? (t - (63 - __clzll((long long)bl))) : 999;
                int dn = ab ? (__ffsll((long long)ab) - 1) : 999;
                int d = min(dp, dn);
                d2a = (d > 63) ? (unsigned)INF16 : (unsigned)(d * d);
            }
            {
                unsigned long long bl = mb & keep, ab = mb >> t;
                int dp = bl ? (t - (63 - __clzll((long long)bl))) : 999;
                int dn = ab ? (__ffsll((long long)ab) - 1) : 999;
                int d = min(dp, dn);
                d2b = (d > 63) ? (unsigned)INF16 : (unsigned)(d * d);
            }
            sv[L][yy * 33 + xp] = d2a | (d2b << 16);
        }
    }
    __syncthreads();

    const unsigned infDup = ((unsigned)INF16 << 16) | (unsigned)INF16;
    unsigned acc[NL][4];

    // ================= y-minplus (j = y, lines = x) =================
    #pragma unroll
    for (int L = 0; L < NL; ++L)
        #pragma unroll
        for (int k = 0; k < 4; ++k) acc[L][k] = 0x7FFF7FFFu;

    #pragma unroll 2
    for (int g = jh * 8; g < jh * 8 + 8; ++g) {
        const int s = i0 + 60 - 4 * g;             // %4==0 -> aligned LDS.128
        const uint4 qa = *(const uint4*)(lut + s);
        const uint4 qb = *(const uint4*)(lut + s + 4);
        unsigned q[8] = { qa.x, qa.y, qa.z, qa.w, qb.x, qb.y, qb.z, qb.w };
        #pragma unroll
        for (int r = 0; r < 4; ++r) {
            #pragma unroll
            for (int L = 0; L < NL; ++L) {
                unsigned vj = sv[L][(4 * g + r) * 33 + cp];
                #pragma unroll
                for (int k = 0; k < 4; ++k)
                    acc[L][k] = __viaddmin_s16x2(vj, q[3 - r + k], acc[L][k]);
            }
        }
    }
    if (jh == 1) {
        #pragma unroll
        for (int L = 0; L < NL; ++L)
            #pragma unroll
            for (int k = 0; k < 4; ++k)
                scr[L][(i0 + k) * 32 + cp] = acc[L][k];
    }
    __syncthreads();
    if (jh == 0) {   // combine halves, clamp, transpose into sw (u16)
        #pragma unroll
        for (int L = 0; L < NL; ++L) {
            unsigned short* sw16 = (unsigned short*)sw[L];
            #pragma unroll
            for (int k = 0; k < 4; ++k) {
                unsigned a = __vminu2(acc[L][k], scr[L][(i0 + k) * 32 + cp]);
                a = __vminu2(a, infDup);           // clamp before next add
                sw16[(2 * cp)     * 66 + i0 + k] = (unsigned short)(a & 0xFFFFu);
                sw16[(2 * cp + 1) * 66 + i0 + k] = (unsigned short)(a >> 16);
            }
        }
    }
    __syncthreads();

    // ================= x-minplus (j = x, lines = y) =================
    #pragma unroll
    for (int L = 0; L < NL; ++L)
        #pragma unroll
        for (int k = 0; k < 4; ++k) acc[L][k] = 0x7FFF7FFFu;

    #pragma unroll 2
    for (int g = jh * 8; g < jh * 8 + 8; ++g) {
        const int s = i0 + 60 - 4 * g;
        const uint4 qa = *(const uint4*)(lut + s);
        const uint4 qb = *(const uint4*)(lut + s + 4);
        unsigned q[8] = { qa.x, qa.y, qa.z, qa.w, qb.x, qb.y, qb.z, qb.w };
        #pragma unroll
        for (int r = 0; r < 4; ++r) {
            #pragma unroll
            for (int L = 0; L < NL; ++L) {
                unsigned vj = sw[L][(4 * g + r) * 33 + cp];
                #pragma unroll
                for (int k = 0; k < 4; ++k)
                    acc[L][k] = __viaddmin_s16x2(vj, q[3 - r + k], acc[L][k]);
            }
        }
    }
    if (jh == 1) {
        #pragma unroll
        for (int L = 0; L < NL; ++L)
            #pragma unroll
            for (int k = 0; k < 4; ++k)
                scr[L][(i0 + k) * 32 + cp] = acc[L][k];
    }
    __syncthreads();
    unsigned short* res16 = (unsigned short*)sv;   // sv is free: reuse as result
    if (jh == 0) {   // combine, write result (y = 2cp(+1), x = i0+k)
        #pragma unroll
        for (int L = 0; L < NL; ++L) {
            #pragma unroll
            for (int k = 0; k < 4; ++k) {
                unsigned a = __vminu2(acc[L][k], scr[L][(i0 + k) * 32 + cp]);
                res16[L * 4224 + (2 * cp)     * 66 + i0 + k] = (unsigned short)(a & 0xFFFFu);
                res16[L * 4224 + (2 * cp + 1) * 66 + i0 + k] = (unsigned short)(a >> 16);
            }
        }
    }
    __syncthreads();

    // ---- fused reduce over this plane (coalesced global reads)
    float local = 0.0f;
    const int pbase = b * VOL + t * 4096;
    #pragma unroll
    for (int e = 0; e < 4; ++e) {
        int v   = e * 1024 + tid;
        int lab = y[pbase + v];
        int yy = v >> 6, xx = v & 63;
        int n0 = res16[0 * 4224 + yy * 66 + xx];
        int n1 = res16[1 * 4224 + yy * 66 + xx];
        int n2 = res16[2 * 4224 + yy * 66 + xx];
        int m = min(lab == 0 ? 0x7FFF : n0,
                min(lab == 1 ? 0x7FFF : n1,
                    lab == 2 ? 0x7FFF : n2));
        float dt = fmaf(W_ANI, sqrtf((float)m), 1.0f);
        float x1 = x[(b * NL + 1) * VOL + t * 4096 + v];
        float x2 = x[(b * NL + 2) * VOL + t * 4096 + v];
        float s  = ((lab == 1) ? (1.0f - x1) : x1)
                 + ((lab == 2) ? (1.0f - x2) : x2);
        local += s * dt;
    }

    #pragma unroll
    for (int o = 16; o; o >>= 1)
        local += __shfl_xor_sync(0xFFFFFFFFu, local, o);
    if ((tid & 31) == 0) wsum[tid >> 5] = local;
    __syncthreads();

    if (tid == 0) {
        float s = 0.0f;
        #pragma unroll
        for (int i = 0; i < 32; ++i) s += wsum[i];
        atomicAdd(&g_acc, (double)s);
        __threadfence();
        unsigned old = atomicAdd(&g_done, 1u);
        if (old == gridDim.x - 1) {          // last block: finalize + reset
            double tot = atomicAdd(&g_acc, 0.0);
            out[0] = (float)(tot / (double)(NB * 2 * VOL) + 1e-5);
            g_acc  = 0.0;
            g_done = 0u;
            __threadfence();
        }
    }
}

// ---------------------------------------------------------------------------
extern "C" void kernel_launch(void* const* d_in, const int* in_sizes, int n_in,
                              void* d_out, int out_size)
{
    const float* x = (const float*)d_in[0];   // (2,3,64,64,64) f32
    const int*   y = (const int*)  d_in[1];   // (2,1,64,64,64) i32
    float* out = (float*)d_out;

    k_masks<<<NB * 64, 256>>>(y);
    k_main <<<NB * 64, 1024>>>(x, y, out);
}

// round 7
// speedup vs baseline: 2.6617x; 1.1888x over previous
#include <cuda_runtime.h>
#include <math.h>

#define VOL   262144    // 64^3
#define NB    2
#define NL    3
#define INF16 25000     // 25000 + 63^2 = 28969 < 32767 (s16-safe)
#define INFDUP 0x61A861A8u
#define W_ANI 0.096f
#define RWIN  8         // window radius; exact when result <= (RWIN+1)^2
#define THR   81        // (RWIN+1)^2

// Per-column z occupancy masks: g_mask[(b*3+L)*4096 + y*64 + x] bit z = (label==L)
__device__ unsigned long long g_mask[NB * NL * 4096];
__device__ double   g_acc;
__device__ unsigned g_done;

// ---------------------------------------------------------------------------
// Kernel A: build z-masks. Block = (b, y).
// ---------------------------------------------------------------------------
__global__ void __launch_bounds__(256)
k_masks(const int* __restrict__ labels)
{
    __shared__ unsigned short smk[NL * 4 * 64];
    const int tid = threadIdx.x;
    const int b = (int)blockIdx.x >> 6, y = (int)blockIdx.x & 63;
    const int x = tid & 63, seg = tid >> 6;

    unsigned m0 = 0, m1 = 0, m2 = 0;
    const int* lp = labels + b * VOL + seg * 16 * 4096 + y * 64 + x;
    #pragma unroll
    for (int zz = 0; zz < 16; ++zz) {
        int lab = lp[zz * 4096];
        m0 |= (lab == 0) ? (1u << zz) : 0u;
        m1 |= (lab == 1) ? (1u << zz) : 0u;
        m2 |= (lab == 2) ? (1u << zz) : 0u;
    }
    smk[(0 * 4 + seg) * 64 + x] = (unsigned short)m0;
    smk[(1 * 4 + seg) * 64 + x] = (unsigned short)m1;
    smk[(2 * 4 + seg) * 64 + x] = (unsigned short)m2;
    __syncthreads();

    if (tid < 192) {
        int L = tid >> 6, xx = tid & 63;
        unsigned long long m =
              (unsigned long long)smk[(L * 4 + 0) * 64 + xx]
            | ((unsigned long long)smk[(L * 4 + 1) * 64 + xx] << 16)
            | ((unsigned long long)smk[(L * 4 + 2) * 64 + xx] << 32)
            | ((unsigned long long)smk[(L * 4 + 3) * 64 + xx] << 48);
        g_mask[(b * NL + L) * 4096 + y * 64 + xx] = m;
    }
}

// ---------------------------------------------------------------------------
// Windowed SIMD min-plus core: buffer rows j in [-8,71] (guards = INF16),
// word [(j+8)*33 + cp] = packed pair. Thread outputs i0..i0+3 for 3 labels.
// d^2 constants are compile-time dup16 immediates (no LUT).
// Returns 1 if any output exceeds THR (window possibly inexact).
// ---------------------------------------------------------------------------
__device__ __forceinline__ int win_minplus(const unsigned* __restrict__ s0,
                                           const unsigned* __restrict__ s1,
                                           const unsigned* __restrict__ s2,
                                           int cp, int i0, unsigned acc[NL][4])
{
    #pragma unroll
    for (int L = 0; L < NL; ++L)
        #pragma unroll
        for (int k = 0; k < 4; ++k) acc[L][k] = 0x7FFF7FFFu;

    #pragma unroll
    for (int m = -RWIN; m <= RWIN + 3; ++m) {
        const int row = (i0 + m + 8) * 33 + cp;
        unsigned v0 = s0[row], v1 = s1[row], v2 = s2[row];
        #pragma unroll
        for (int k = 0; k < 4; ++k) {
            const int d = m - k;
            if (d < -RWIN || d > RWIN) continue;
            const unsigned q = (unsigned)(d * d) * 0x10001u;   // immediate
            acc[0][k] = __viaddmin_s16x2(v0, q, acc[0][k]);
            acc[1][k] = __viaddmin_s16x2(v1, q, acc[1][k]);
            acc[2][k] = __viaddmin_s16x2(v2, q, acc[2][k]);
        }
    }
    unsigned mx = 0;
    #pragma unroll
    for (int L = 0; L < NL; ++L)
        #pragma unroll
        for (int k = 0; k < 4; ++k) mx = __vmaxu2(mx, acc[L][k]);
    return ((mx & 0xFFFFu) > THR) | ((mx >> 16) > THR);
}

// Full 64-candidate fallback (sound path; not taken on typical data).
__device__ __forceinline__ void full_minplus(const unsigned* __restrict__ s0,
                                             const unsigned* __restrict__ s1,
                                             const unsigned* __restrict__ s2,
                                             int cp, int i0, unsigned acc[NL][4])
{
    #pragma unroll
    for (int L = 0; L < NL; ++L)
        #pragma unroll
        for (int k = 0; k < 4; ++k) acc[L][k] = 0x7FFF7FFFu;
    for (int j = 0; j < 64; ++j) {
        const int row = (j + 8) * 33 + cp;
        unsigned v0 = s0[row], v1 = s1[row], v2 = s2[row];
        #pragma unroll
        for (int k = 0; k < 4; ++k) {
            int d = j - (i0 + k);
            unsigned q = (unsigned)(d * d) * 0x10001u;
            acc[0][k] = __viaddmin_s16x2(v0, q, acc[0][k]);
            acc[1][k] = __viaddmin_s16x2(v1, q, acc[1][k]);
            acc[2][k] = __viaddmin_s16x2(v2, q, acc[2][k]);
        }
    }
}

// ---------------------------------------------------------------------------
// Kernel B: block = (b, z-plane t), 128 blocks x 512 threads.
// z-vals from masks -> windowed y-minplus (+fallback) -> transpose ->
// windowed x-minplus (+fallback) -> fused masked reduce -> finalize.
// ---------------------------------------------------------------------------
__global__ void __launch_bounds__(512, 1)
k_main(const float* __restrict__ x, const int* __restrict__ y,
       float* __restrict__ out)
{
    __shared__ unsigned sv[NL][80 * 33];   // rows -8..71 (guards), also final res
    __shared__ unsigned sw[NL][80 * 33];   // y-result transposed, with guards
    __shared__ float    wsum[16];

    const int tid = threadIdx.x;
    const int b  = (int)blockIdx.x >> 6, t = (int)blockIdx.x & 63;
    const int cp = tid & 31;
    const int i0 = (tid >> 5) * 4;

    // ---- guard rows for sv (j = -8..-1, 64..71)
    for (int w = tid; w < NL * 512; w += 512) {
        int L = w >> 9, idx = w & 511;
        int r = idx >> 5, c = idx & 31;
        int row = (r < 8) ? r : (r + 64);
        sv[L][row * 33 + c] = INFDUP;
    }

    // ---- z-pass values for all 3 labels from masks
    const unsigned long long keep = ~0ULL >> (63 - t);
    #pragma unroll
    for (int L = 0; L < NL; ++L) {
        const uint4* mp = (const uint4*)&g_mask[(b * NL + L) * 4096];
        #pragma unroll
        for (int e = 0; e < 4; ++e) {
            int widx = e * 512 + tid;
            int yy = widx >> 5, xp = widx & 31;
            uint4 mm = mp[widx];
            unsigned long long ma = ((unsigned long long)mm.y << 32) | mm.x;
            unsigned long long mb = ((unsigned long long)mm.w << 32) | mm.z;
            unsigned d2a, d2b;
            {
                unsigned long long bl = ma & keep, ab = ma >> t;
                int dp = bl ? (t - (63 - __clzll((long long)bl))) : 999;
                int dn = ab ? (__ffsll((long long)ab) - 1) : 999;
                int d = min(dp, dn);
                d2a = (d > 63) ? (unsigned)INF16 : (unsigned)(d * d);
            }
            {
                unsigned long long bl = mb & keep, ab = mb >> t;
                int dp = bl ? (t - (63 - __clzll((long long)bl))) : 999;
                int dn = ab ? (__ffsll((long long)ab) - 1) : 999;
                int d = min(dp, dn);
                d2b = (d > 63) ? (unsigned)INF16 : (unsigned)(d * d);
            }
            sv[L][(yy + 8) * 33 + xp] = d2a | (d2b << 16);
        }
    }
    __syncthreads();

    unsigned acc[NL][4];

    // ================= y-minplus (j = y, lines = x) =================
    int bad = win_minplus(sv[0], sv[1], sv[2], cp, i0, acc);
    if (__syncthreads_or(bad))
        full_minplus(sv[0], sv[1], sv[2], cp, i0, acc);

    // clamp + transposed write into sw (u16), plus sw guard rows
    for (int w = tid; w < NL * 512; w += 512) {
        int L = w >> 9, idx = w & 511;
        int r = idx >> 5, c = idx & 31;
        int row = (r < 8) ? r : (r + 64);
        sw[L][row * 33 + c] = INFDUP;
    }
    #pragma unroll
    for (int L = 0; L < NL; ++L) {
        unsigned short* sw16 = (unsigned short*)sw[L];
        #pragma unroll
        for (int k = 0; k < 4; ++k) {
            unsigned a = __vminu2(acc[L][k], INFDUP);
            sw16[(2 * cp + 8) * 66 + (i0 + k) + 8 * 66 - 8 * 66] = 0; // (placeholder removed below)
        }
    }
    // NOTE: real transposed write (row offset +8 along scan axis x):
    #pragma unroll
    for (int L = 0; L < NL; ++L) {
        unsigned short* sw16 = (unsigned short*)sw[L];
        #pragma unroll
        for (int k = 0; k < 4; ++k) {
            unsigned a = __vminu2(acc[L][k], INFDUP);
            sw16[(2 * cp + 8) * 66 + (i0 + k)]     = (unsigned short)(a & 0xFFFFu);
            sw16[(2 * cp + 1 + 8) * 66 + (i0 + k)] = (unsigned short)(a >> 16);
        }
    }
    __syncthreads();

    // ================= x-minplus (j = x, lines = y) =================
    bad = win_minplus(sw[0], sw[1], sw[2], cp, i0, acc);
    if (__syncthreads_or(bad))
        full_minplus(sw[0], sw[1], sw[2], cp, i0, acc);

    // result res16[y*66 + x] (reuse sv)
    #pragma unroll
    for (int L = 0; L < NL; ++L) {
        unsigned short* res16 = (unsigned short*)sv[L];
        #pragma unroll
        for (int k = 0; k < 4; ++k) {
            res16[(2 * cp) * 66 + (i0 + k)]     = (unsigned short)(acc[L][k] & 0xFFFFu);
            res16[(2 * cp + 1) * 66 + (i0 + k)] = (unsigned short)(acc[L][k] >> 16);
        }
    }
    __syncthreads();

    // ---- fused reduce over this plane
    float local = 0.0f;
    const int pbase = b * VOL + t * 4096;
    const unsigned short* r0 = (const unsigned short*)sv[0];
    const unsigned short* r1 = (const unsigned short*)sv[1];
    const unsigned short* r2 = (const unsigned short*)sv[2];
    #pragma unroll
    for (int e = 0; e < 8; ++e) {
        int v   = e * 512 + tid;
        int lab = y[pbase + v];
        int yy = v >> 6, xx = v & 63;
        int n0 = r0[yy * 66 + xx];
        int n1 = r1[yy * 66 + xx];
        int n2 = r2[yy * 66 + xx];
        int m = min(lab == 0 ? 0x7FFF : n0,
                min(lab == 1 ? 0x7FFF : n1,
                    lab == 2 ? 0x7FFF : n2));
        float dt = fmaf(W_ANI, sqrtf((float)m), 1.0f);
        float x1 = x[(b * NL + 1) * VOL + t * 4096 + v];
        float x2 = x[(b * NL + 2) * VOL + t * 4096 + v];
        float s  = ((lab == 1) ? (1.0f - x1) : x1)
                 + ((lab == 2) ? (1.0f - x2) : x2);
        local += s * dt;
    }

    #pragma unroll
    for (int o = 16; o; o >>= 1)
        local += __shfl_xor_sync(0xFFFFFFFFu, local, o);
    if ((tid & 31) == 0) wsum[tid >> 5] = local;
    __syncthreads();

    if (tid == 0) {
        float s = 0.0f;
        #pragma unroll
        for (int i = 0; i < 16; ++i) s += wsum[i];
        atomicAdd(&g_acc, (double)s);
        __threadfence();
        unsigned old = atomicAdd(&g_done, 1u);
        if (old == gridDim.x - 1) {
            double tot = atomicAdd(&g_acc, 0.0);
            out[0] = (float)(tot / (double)(NB * 2 * VOL) + 1e-5);
            g_acc  = 0.0;
            g_done = 0u;
            __threadfence();
        }
    }
}

// ---------------------------------------------------------------------------
extern "C" void kernel_launch(void* const* d_in, const int* in_sizes, int n_in,
                              void* d_out, int out_size)
{
    const float* x = (const float*)d_in[0];   // (2,3,64,64,64) f32
    const int*   y = (const int*)  d_in[1];   // (2,1,64,64,64) i32
    float* out = (float*)d_out;

    k_masks<<<NB * 64, 256>>>(y);
    k_main <<<NB * 64, 512>>>(x, y, out);
}

// round 8
// speedup vs baseline: 2.6817x; 1.0075x over previous
#include <cuda_runtime.h>
#include <math.h>

#define VOL   262144    // 64^3
#define NB    2
#define NL    3
#define INF16 25000     // 25000 + 63^2 = 28969 < 32767 (s16-safe)
#define INFDUP 0x61A861A8u
#define W_ANI 0.096f
#define RWIN  8         // window radius; exact when result <= (RWIN+1)^2
#define THR   81        // (RWIN+1)^2

// Per-column z occupancy masks: g_mask[(b*3+L)*4096 + y*64 + x] bit z = (label==L)
__device__ unsigned long long g_mask[NB * NL * 4096];
__device__ double   g_acc;
__device__ unsigned g_done;

// ---------------------------------------------------------------------------
// Kernel A: build z-masks. Block = (b, y).
// ---------------------------------------------------------------------------
__global__ void __launch_bounds__(256)
k_masks(const int* __restrict__ labels)
{
    __shared__ unsigned short smk[NL * 4 * 64];
    const int tid = threadIdx.x;
    const int b = (int)blockIdx.x >> 6, y = (int)blockIdx.x & 63;
    const int x = tid & 63, seg = tid >> 6;

    unsigned m0 = 0, m1 = 0, m2 = 0;
    const int* lp = labels + b * VOL + seg * 16 * 4096 + y * 64 + x;
    #pragma unroll
    for (int zz = 0; zz < 16; ++zz) {
        int lab = lp[zz * 4096];
        m0 |= (lab == 0) ? (1u << zz) : 0u;
        m1 |= (lab == 1) ? (1u << zz) : 0u;
        m2 |= (lab == 2) ? (1u << zz) : 0u;
    }
    smk[(0 * 4 + seg) * 64 + x] = (unsigned short)m0;
    smk[(1 * 4 + seg) * 64 + x] = (unsigned short)m1;
    smk[(2 * 4 + seg) * 64 + x] = (unsigned short)m2;
    __syncthreads();

    if (tid < 192) {
        int L = tid >> 6, xx = tid & 63;
        unsigned long long m =
              (unsigned long long)smk[(L * 4 + 0) * 64 + xx]
            | ((unsigned long long)smk[(L * 4 + 1) * 64 + xx] << 16)
            | ((unsigned long long)smk[(L * 4 + 2) * 64 + xx] << 32)
            | ((unsigned long long)smk[(L * 4 + 3) * 64 + xx] << 48);
        g_mask[(b * NL + L) * 4096 + y * 64 + xx] = m;
    }
}

// z squared-distance at plane t from a column mask
__device__ __forceinline__ unsigned zdist2(unsigned long long m, int t,
                                           unsigned long long keep)
{
    unsigned long long bl = m & keep, ab = m >> t;
    int dp = bl ? (t - (63 - __clzll((long long)bl))) : 999;
    int dn = ab ? (__ffsll((long long)ab) - 1) : 999;
    int d = min(dp, dn);
    return (d > 63) ? (unsigned)INF16 : (unsigned)(d * d);
}

// ---------------------------------------------------------------------------
// Windowed SIMD min-plus: rows (i0+m+8)*PITCH + lane, m = -8..11, d^2 as
// compile-time dup16 immediates. Returns 1 if any output > THR (inexact risk).
// ---------------------------------------------------------------------------
template<int PITCH>
__device__ __forceinline__ int win_minplus(const unsigned* __restrict__ s0,
                                           const unsigned* __restrict__ s1,
                                           const unsigned* __restrict__ s2,
                                           int lane, int i0, unsigned acc[NL][4])
{
    #pragma unroll
    for (int L = 0; L < NL; ++L)
        #pragma unroll
        for (int k = 0; k < 4; ++k) acc[L][k] = 0x7FFF7FFFu;

    #pragma unroll
    for (int m = -RWIN; m <= RWIN + 3; ++m) {
        const int row = (i0 + m + 8) * PITCH + lane;
        unsigned v0 = s0[row], v1 = s1[row], v2 = s2[row];
        #pragma unroll
        for (int k = 0; k < 4; ++k) {
            const int d = m - k;
            if (d < -RWIN || d > RWIN) continue;
            const unsigned q = (unsigned)(d * d) * 0x10001u;
            acc[0][k] = __viaddmin_s16x2(v0, q, acc[0][k]);
            acc[1][k] = __viaddmin_s16x2(v1, q, acc[1][k]);
            acc[2][k] = __viaddmin_s16x2(v2, q, acc[2][k]);
        }
    }
    unsigned mx = 0;
    #pragma unroll
    for (int L = 0; L < NL; ++L)
        #pragma unroll
        for (int k = 0; k < 4; ++k) mx = __vmaxu2(mx, acc[L][k]);
    return ((mx & 0xFFFFu) > THR) | ((mx >> 16) > THR);
}

// ---------------------------------------------------------------------------
// Kernel B: block = (b, z-plane t, y-half h). 256 blocks x 256 threads
// (2 resident/SM -> cross-block latency hiding).
// z-vals (+8 halo) from masks -> windowed y-minplus (mask-exact fallback) ->
// transpose -> windowed x-minplus (sw-exact fallback) -> fused reduce.
// Reduce operands prefetched into registers at kernel entry.
// ---------------------------------------------------------------------------
__global__ void __launch_bounds__(256, 2)
k_main(const float* __restrict__ x, const int* __restrict__ y,
       float* __restrict__ out)
{
    __shared__ unsigned sv[NL][48 * 33];   // z-vals rows y0-8..y0+39; reused as res
    __shared__ unsigned sw[NL][80 * 17];   // y-result transposed (x rows -8..71)
    __shared__ float    wsum[8];

    const int tid = threadIdx.x;
    const int bid = (int)blockIdx.x;
    const int b   = bid >> 7;
    const int t   = (bid & 127) >> 1;
    const int y0  = (bid & 1) * 32;

    // ---- prefetch reduce operands (consumed at the end; 24 LDGs in flight)
    const int gbase = b * VOL + t * 4096 + y0 * 64;
    int   plab[8];
    float px1[8], px2[8];
    #pragma unroll
    for (int e = 0; e < 8; ++e) {
        int v = e * 256 + tid;
        plab[e] = y[gbase + v];
        px1[e]  = x[(b * NL + 1) * VOL + t * 4096 + y0 * 64 + v];
        px2[e]  = x[(b * NL + 2) * VOL + t * 4096 + y0 * 64 + v];
    }

    // ---- z-pass values for tile rows y0-8 .. y0+39 (48 rows), all labels
    const unsigned long long keep = ~0ULL >> (63 - t);
    #pragma unroll
    for (int e = 0; e < 6; ++e) {
        int widx = e * 256 + tid;              // 0..1535
        int r = widx >> 5, xp = widx & 31;
        int ygl = y0 - 8 + r;
        bool valid = ((unsigned)ygl < 64u);
        #pragma unroll
        for (int L = 0; L < NL; ++L) {
            unsigned word = INFDUP;
            if (valid) {
                uint4 mm = ((const uint4*)&g_mask[(b * NL + L) * 4096])[ygl * 32 + xp];
                unsigned long long ma = ((unsigned long long)mm.y << 32) | mm.x;
                unsigned long long mb = ((unsigned long long)mm.w << 32) | mm.z;
                word = zdist2(ma, t, keep) | (zdist2(mb, t, keep) << 16);
            }
            sv[L][r * 33 + xp] = word;
        }
    }
    // sw guard rows (x = -8..-1, 64..71)
    for (int w = tid; w < NL * 16 * 17; w += 256) {
        int L = w / 272, rem = w - L * 272;
        int rr = rem / 17, c = rem - rr * 17;
        int row = (rr < 8) ? rr : (rr + 64);
        sw[L][row * 17 + c] = INFDUP;
    }
    __syncthreads();

    unsigned acc[NL][4];

    // ================= y-minplus (scan y, lines = x) =================
    const int cp = tid & 31;                   // x-pair
    const int i0 = (tid >> 5) * 4;             // local y outputs i0..i0+3
    int bad = win_minplus<33>(sv[0], sv[1], sv[2], cp, i0, acc);
    if (__syncthreads_or(bad)) {
        // exact fallback straight from masks (sound; cold path)
        #pragma unroll
        for (int L = 0; L < NL; ++L)
            #pragma unroll
            for (int k = 0; k < 4; ++k) acc[L][k] = 0x7FFF7FFFu;
        for (int j = 0; j < 64; ++j) {
            #pragma unroll
            for (int L = 0; L < NL; ++L) {
                const unsigned long long* mp64 = &g_mask[(b * NL + L) * 4096 + j * 64];
                unsigned vj = zdist2(mp64[2 * cp], t, keep)
                            | (zdist2(mp64[2 * cp + 1], t, keep) << 16);
                #pragma unroll
                for (int k = 0; k < 4; ++k) {
                    int d = j - (y0 + i0 + k);
                    unsigned q = (unsigned)(d * d) * 0x10001u;
                    acc[L][k] = __viaddmin_s16x2(vj, q, acc[L][k]);
                }
            }
        }
    }
    // clamp + transposed write into sw: value (ylocal=i0+k, x=2cp+s)
    #pragma unroll
    for (int L = 0; L < NL; ++L) {
        unsigned short* sw16 = (unsigned short*)sw[L];
        #pragma unroll
        for (int k = 0; k < 4; ++k) {
            unsigned a = __vminu2(acc[L][k], INFDUP);
            sw16[(2 * cp + 8) * 34 + (i0 + k)]     = (unsigned short)(a & 0xFFFFu);
            sw16[(2 * cp + 9) * 34 + (i0 + k)]     = (unsigned short)(a >> 16);
        }
    }
    __syncthreads();

    // ================= x-minplus (scan x, lines = y) =================
    const int cp2 = tid & 15;                  // y-pair
    const int j0  = (tid >> 4) * 4;            // x outputs j0..j0+3
    bad = win_minplus<17>(sw[0], sw[1], sw[2], cp2, j0, acc);
    if (__syncthreads_or(bad)) {
        #pragma unroll
        for (int L = 0; L < NL; ++L)
            #pragma unroll
            for (int k = 0; k < 4; ++k) acc[L][k] = 0x7FFF7FFFu;
        for (int j = 0; j < 64; ++j) {
            #pragma unroll
            for (int L = 0; L < NL; ++L) {
                unsigned vj = sw[L][(j + 8) * 17 + cp2];
                #pragma unroll
                for (int k = 0; k < 4; ++k) {
                    int d = j - (j0 + k);
                    unsigned q = (unsigned)(d * d) * 0x10001u;
                    acc[L][k] = __viaddmin_s16x2(vj, q, acc[L][k]);
                }
            }
        }
    }
    // write result res16[ylocal*66 + x] (reuse sv; last sv read was pre-sync)
    #pragma unroll
    for (int L = 0; L < NL; ++L) {
        unsigned short* res16 = (unsigned short*)sv[L];
        #pragma unroll
        for (int k = 0; k < 4; ++k) {
            res16[(2 * cp2)     * 66 + (j0 + k)] = (unsigned short)(acc[L][k] & 0xFFFFu);
            res16[(2 * cp2 + 1) * 66 + (j0 + k)] = (unsigned short)(acc[L][k] >> 16);
        }
    }
    __syncthreads();

    // ---- fused reduce over this half-plane (operands already in registers)
    const unsigned short* r0 = (const unsigned short*)sv[0];
    const unsigned short* r1 = (const unsigned short*)sv[1];
    const unsigned short* r2 = (const unsigned short*)sv[2];
    float local = 0.0f;
    #pragma unroll
    for (int e = 0; e < 8; ++e) {
        int v   = e * 256 + tid;
        int lab = plab[e];
        int yy = v >> 6, xx = v & 63;
        int n0 = r0[yy * 66 + xx];
        int n1 = r1[yy * 66 + xx];
        int n2 = r2[yy * 66 + xx];
        int m = min(lab == 0 ? 0x7FFF : n0,
                min(lab == 1 ? 0x7FFF : n1,
                    lab == 2 ? 0x7FFF : n2));
        float dt = fmaf(W_ANI, sqrtf((float)m), 1.0f);
        float s  = ((lab == 1) ? (1.0f - px1[e]) : px1[e])
                 + ((lab == 2) ? (1.0f - px2[e]) : px2[e]);
        local += s * dt;
    }

    #pragma unroll
    for (int o = 16; o; o >>= 1)
        local += __shfl_xor_sync(0xFFFFFFFFu, local, o);
    if ((tid & 31) == 0) wsum[tid >> 5] = local;
    __syncthreads();

    if (tid == 0) {
        float s = 0.0f;
        #pragma unroll
        for (int i = 0; i < 8; ++i) s += wsum[i];
        atomicAdd(&g_acc, (double)s);
        __threadfence();
        unsigned old = atomicAdd(&g_done, 1u);
        if (old == gridDim.x - 1) {            // last block: finalize + reset
            double tot = atomicAdd(&g_acc, 0.0);
            out[0] = (float)(tot / (double)(NB * 2 * VOL) + 1e-5);
            g_acc  = 0.0;
            g_done = 0u;
            __threadfence();
        }
    }
}

// ---------------------------------------------------------------------------
extern "C" void kernel_launch(void* const* d_in, const int* in_sizes, int n_in,
                              void* d_out, int out_size)
{
    const float* x = (const float*)d_in[0];   // (2,3,64,64,64) f32
    const int*   y = (const int*)  d_in[1];   // (2,1,64,64,64) i32
    float* out = (float*)d_out;

    k_masks<<<NB * 64, 256>>>(y);
    k_main <<<NB * 128, 256>>>(x, y, out);
}

// round 10
// speedup vs baseline: 2.7021x; 1.0076x over previous
#include <cuda_runtime.h>
#include <math.h>

#define VOL   262144    // 64^3
#define NB    2
#define NL    3
#define INF16 25000     // 25000 + 63^2 = 28969 < 32767 (s16-safe)
#define INFDUP 0x61A861A8u
#define W_ANI 0.096f
#define RWIN  8         // window radius; exact when result <= (RWIN+1)^2
#define THR   81        // (RWIN+1)^2

// Per-column z occupancy masks: g_mask[(b*3+L)*4096 + y*64 + x] bit z = (label==L)
__device__ unsigned long long g_mask[NB * NL * 4096];
__device__ double   g_acc;
__device__ unsigned g_done;

// ---------------------------------------------------------------------------
// Kernel A: build z-masks. Block = (b, y).
// ---------------------------------------------------------------------------
__global__ void __launch_bounds__(256)
k_masks(const int* __restrict__ labels)
{
    __shared__ unsigned short smk[NL * 4 * 64];
    const int tid = threadIdx.x;
    const int b = (int)blockIdx.x >> 6, y = (int)blockIdx.x & 63;
    const int x = tid & 63, seg = tid >> 6;

    unsigned m0 = 0, m1 = 0, m2 = 0;
    const int* lp = labels + b * VOL + seg * 16 * 4096 + y * 64 + x;
    #pragma unroll
    for (int zz = 0; zz < 16; ++zz) {
        int lab = lp[zz * 4096];
        m0 |= (lab == 0) ? (1u << zz) : 0u;
        m1 |= (lab == 1) ? (1u << zz) : 0u;
        m2 |= (lab == 2) ? (1u << zz) : 0u;
    }
    smk[(0 * 4 + seg) * 64 + x] = (unsigned short)m0;
    smk[(1 * 4 + seg) * 64 + x] = (unsigned short)m1;
    smk[(2 * 4 + seg) * 64 + x] = (unsigned short)m2;
    __syncthreads();

    if (tid < 192) {
        int L = tid >> 6, xx = tid & 63;
        unsigned long long m =
              (unsigned long long)smk[(L * 4 + 0) * 64 + xx]
            | ((unsigned long long)smk[(L * 4 + 1) * 64 + xx] << 16)
            | ((unsigned long long)smk[(L * 4 + 2) * 64 + xx] << 32)
            | ((unsigned long long)smk[(L * 4 + 3) * 64 + xx] << 48);
        g_mask[(b * NL + L) * 4096 + y * 64 + xx] = m;
    }
}

// z squared-distance at plane t from a column mask
__device__ __forceinline__ unsigned zdist2(unsigned long long m, int t,
                                           unsigned long long keep)
{
    unsigned long long bl = m & keep, ab = m >> t;
    int dp = bl ? (t - (63 - __clzll((long long)bl))) : 999;
    int dn = ab ? (__ffsll((long long)ab) - 1) : 999;
    int d = min(dp, dn);
    return (d > 63) ? (unsigned)INF16 : (unsigned)(d * d);
}

// ---------------------------------------------------------------------------
// Windowed SIMD min-plus: rows (i0+m+8)*PITCH + lane, m = -8..11, d^2 as
// compile-time dup16 immediates. Returns 1 if any output > THR (inexact risk).
// ---------------------------------------------------------------------------
template<int PITCH>
__device__ __forceinline__ int win_minplus(const unsigned* __restrict__ s0,
                                           const unsigned* __restrict__ s1,
                                           const unsigned* __restrict__ s2,
                                           int lane, int i0, unsigned acc[NL][4])
{
    #pragma unroll
    for (int L = 0; L < NL; ++L)
        #pragma unroll
        for (int k = 0; k < 4; ++k) acc[L][k] = 0x7FFF7FFFu;

    #pragma unroll
    for (int m = -RWIN; m <= RWIN + 3; ++m) {
        const int row = (i0 + m + 8) * PITCH + lane;
        unsigned v0 = s0[row], v1 = s1[row], v2 = s2[row];
        #pragma unroll
        for (int k = 0; k < 4; ++k) {
            const int d = m - k;
            if (d < -RWIN || d > RWIN) continue;
            const unsigned q = (unsigned)(d * d) * 0x10001u;
            acc[0][k] = __viaddmin_s16x2(v0, q, acc[0][k]);
            acc[1][k] = __viaddmin_s16x2(v1, q, acc[1][k]);
            acc[2][k] = __viaddmin_s16x2(v2, q, acc[2][k]);
        }
    }
    unsigned mx = 0;
    #pragma unroll
    for (int L = 0; L < NL; ++L)
        #pragma unroll
        for (int k = 0; k < 4; ++k) mx = __vmaxu2(mx, acc[L][k]);
    return ((mx & 0xFFFFu) > THR) | ((mx >> 16) > THR);
}

// ---------------------------------------------------------------------------
// Kernel B: block = (b, z-plane t, y-half). 256 blocks x 256 threads.
// Penalty weights s[e] computed at entry (distance-independent) so only
// 9 registers stay live across the min-plus phases. dt via shared LUT when
// the windowed passes were exact (always on typical data).
// ---------------------------------------------------------------------------
__global__ void __launch_bounds__(256, 2)
k_main(const float* __restrict__ x, const int* __restrict__ y,
       float* __restrict__ out)
{
    __shared__ unsigned sv[NL][48 * 33];   // z-vals rows y0-8..y0+39; reused as res
    __shared__ unsigned sw[NL][80 * 17];   // y-result transposed (x rows -8..71)
    __shared__ float    dtlut[THR + 1];    // w*sqrt(m)+1 for m=0..81
    __shared__ float    wsum[8];

    const int tid = threadIdx.x;
    const int bid = (int)blockIdx.x;
    const int b   = bid >> 7;
    const int t   = (bid & 127) >> 1;
    const int y0  = (bid & 1) * 32;

    // ---- dt LUT (hidden under the mask-load phase)
    if (tid <= THR) dtlut[tid] = fmaf(W_ANI, sqrtf((float)tid), 1.0f);

    // ---- entry prefetch, consumed immediately: s[e] + packed labels
    const int gbase = b * VOL + t * 4096 + y0 * 64;
    float s8[8];
    unsigned labp = 0;
    #pragma unroll
    for (int e = 0; e < 8; ++e) {
        int v = e * 256 + tid;
        int lab = y[gbase + v];
        float x1 = x[(b * NL + 1) * VOL + gbase - b * VOL * 0 + v - b * 0];  // see below
        float x2 = x[(b * NL + 2) * VOL + t * 4096 + y0 * 64 + v];
        x1 = x[(b * NL + 1) * VOL + t * 4096 + y0 * 64 + v];
        s8[e] = ((lab == 1) ? (1.0f - x1) : x1)
              + ((lab == 2) ? (1.0f - x2) : x2);
        labp |= (unsigned)lab << (2 * e);
    }

    // ---- z-pass values for tile rows y0-8 .. y0+39 (48 rows), all labels
    const unsigned long long keep = ~0ULL >> (63 - t);
    #pragma unroll
    for (int e = 0; e < 6; ++e) {
        int widx = e * 256 + tid;              // 0..1535
        int r = widx >> 5, xp = widx & 31;
        int ygl = y0 - 8 + r;
        bool valid = ((unsigned)ygl < 64u);
        #pragma unroll
        for (int L = 0; L < NL; ++L) {
            unsigned word = INFDUP;
            if (valid) {
                uint4 mm = ((const uint4*)&g_mask[(b * NL + L) * 4096])[ygl * 32 + xp];
                unsigned long long ma = ((unsigned long long)mm.y << 32) | mm.x;
                unsigned long long mb = ((unsigned long long)mm.w << 32) | mm.z;
                word = zdist2(ma, t, keep) | (zdist2(mb, t, keep) << 16);
            }
            sv[L][r * 33 + xp] = word;
        }
    }
    // sw guard rows (x = -8..-1, 64..71)
    for (int w = tid; w < NL * 16 * 17; w += 256) {
        int L = w / 272, rem = w - L * 272;
        int rr = rem / 17, c = rem - rr * 17;
        int row = (rr < 8) ? rr : (rr + 64);
        sw[L][row * 17 + c] = INFDUP;
    }
    __syncthreads();

    unsigned acc[NL][4];

    // ================= y-minplus (scan y, lines = x) =================
    const int cp = tid & 31;                   // x-pair
    const int i0 = (tid >> 5) * 4;             // local y outputs i0..i0+3
    int bad = win_minplus<33>(sv[0], sv[1], sv[2], cp, i0, acc);
    const int fb1 = __syncthreads_or(bad);
    if (fb1) {
        // exact fallback straight from masks (sound; cold path)
        #pragma unroll
        for (int L = 0; L < NL; ++L)
            #pragma unroll
            for (int k = 0; k < 4; ++k) acc[L][k] = 0x7FFF7FFFu;
        for (int j = 0; j < 64; ++j) {
            #pragma unroll
            for (int L = 0; L < NL; ++L) {
                const unsigned long long* mp64 = &g_mask[(b * NL + L) * 4096 + j * 64];
                unsigned vj = zdist2(mp64[2 * cp], t, keep)
                            | (zdist2(mp64[2 * cp + 1], t, keep) << 16);
                #pragma unroll
                for (int k = 0; k < 4; ++k) {
                    int d = j - (y0 + i0 + k);
                    unsigned q = (unsigned)(d * d) * 0x10001u;
                    acc[L][k] = __viaddmin_s16x2(vj, q, acc[L][k]);
                }
            }
        }
    }
    // clamp + transposed write into sw: value (ylocal=i0+k, x=2cp+s)
    #pragma unroll
    for (int L = 0; L < NL; ++L) {
        unsigned short* sw16 = (unsigned short*)sw[L];
        #pragma unroll
        for (int k = 0; k < 4; ++k) {
            unsigned a = __vminu2(acc[L][k], INFDUP);
            sw16[(2 * cp + 8) * 34 + (i0 + k)] = (unsigned short)(a & 0xFFFFu);
            sw16[(2 * cp + 9) * 34 + (i0 + k)] = (unsigned short)(a >> 16);
        }
    }
    __syncthreads();

    // ================= x-minplus (scan x, lines = y) =================
    const int cp2 = tid & 15;                  // y-pair
    const int j0  = (tid >> 4) * 4;            // x outputs j0..j0+3
    bad = win_minplus<17>(sw[0], sw[1], sw[2], cp2, j0, acc);
    const int fb2 = __syncthreads_or(bad);
    if (fb2) {
        #pragma unroll
        for (int L = 0; L < NL; ++L)
            #pragma unroll
            for (int k = 0; k < 4; ++k) acc[L][k] = 0x7FFF7FFFu;
        for (int j = 0; j < 64; ++j) {
            #pragma unroll
            for (int L = 0; L < NL; ++L) {
                unsigned vj = sw[L][(j + 8) * 17 + cp2];
                #pragma unroll
                for (int k = 0; k < 4; ++k) {
                    int d = j - (j0 + k);
                    unsigned q = (unsigned)(d * d) * 0x10001u;
                    acc[L][k] = __viaddmin_s16x2(vj, q, acc[L][k]);
                }
            }
        }
    }
    // write result res16[ylocal*66 + x] (reuse sv)
    #pragma unroll
    for (int L = 0; L < NL; ++L) {
        unsigned short* res16 = (unsigned short*)sv[L];
        #pragma unroll
        for (int k = 0; k < 4; ++k) {
            res16[(2 * cp2)     * 66 + (j0 + k)] = (unsigned short)(acc[L][k] & 0xFFFFu);
            res16[(2 * cp2 + 1) * 66 + (j0 + k)] = (unsigned short)(acc[L][k] >> 16);
        }
    }
    __syncthreads();

    // ---- fused reduce: weights already in registers, dt via LUT (hot path)
    const unsigned short* r0 = (const unsigned short*)sv[0];
    const unsigned short* r1 = (const unsigned short*)sv[1];
    const unsigned short* r2 = (const unsigned short*)sv[2];
    const bool exact = !(fb1 | fb2);           // block-uniform
    float local = 0.0f;
    #pragma unroll
    for (int e = 0; e < 8; ++e) {
        int v   = e * 256 + tid;
        int lab = (labp >> (2 * e)) & 3;
        int yy = v >> 6, xx = v & 63;
        int n0 = r0[yy * 66 + xx];
        int n1 = r1[yy * 66 + xx];
        int n2 = r2[yy * 66 + xx];
        int m = min(lab == 0 ? 0x7FFF : n0,
                min(lab == 1 ? 0x7FFF : n1,
                    lab == 2 ? 0x7FFF : n2));
        float dt = exact ? dtlut[m]
                         : fmaf(W_ANI, sqrtf((float)m), 1.0f);
        local += s8[e] * dt;
    }

    #pragma unroll
    for (int o = 16; o; o >>= 1)
        local += __shfl_xor_sync(0xFFFFFFFFu, local, o);
    if ((tid & 31) == 0) wsum[tid >> 5] = local;
    __syncthreads();

    if (tid == 0) {
        float s = 0.0f;
        #pragma unroll
        for (int i = 0; i < 8; ++i) s += wsum[i];
        atomicAdd(&g_acc, (double)s);
        __threadfence();
        unsigned old = atomicAdd(&g_done, 1u);
        if (old == gridDim.x - 1) {            // last block: finalize + reset
            double tot = atomicAdd(&g_acc, 0.0);
            out[0] = (float)(tot / (double)(NB * 2 * VOL) + 1e-5);
            g_acc  = 0.0;
            g_done = 0u;
            __threadfence();
        }
    }
}

// ---------------------------------------------------------------------------
extern "C" void kernel_launch(void* const* d_in, const int* in_sizes, int n_in,
                              void* d_out, int out_size)
{
    const float* x = (const float*)d_in[0];   // (2,3,64,64,64) f32
    const int*   y = (const int*)  d_in[1];   // (2,1,64,64,64) i32
    float* out = (float*)d_out;

    k_masks<<<NB * 64, 256>>>(y);
    k_main <<<NB * 128, 256>>>(x, y, out);
}

// round 12
// speedup vs baseline: 3.0690x; 1.1358x over previous
#include <cuda_runtime.h>
#include <math.h>

#define VOL   262144    // 64^3
#define FW    131072    // u32 words per (b,L) field
#define NB    2
#define NL    3
#define INF16 25000     // 25000 + 63^2 = 28969 < 32767 (s16-safe)
#define INFDUP 0x61A861A8u
#define W_ANI 0.096f
#define RWIN  8         // window radius; exact when result <= (RWIN+1)^2
#define THR   81        // (RWIN+1)^2

// z-pass squared-distance field, u16 packed in u32: [(b*3+L)][z][y][x/2]
__device__ unsigned g_zf32[NB * NL * FW];   // 3 MB
__device__ double   g_acc;
__device__ unsigned g_done;

// ---------------------------------------------------------------------------
// Kernel A: per-(b,y) build column masks, scan -> z-distance^2 for all
// (L, z, x), coalesced store of the full z-field slab.
// ---------------------------------------------------------------------------
__global__ void __launch_bounds__(256)
k_zfield(const int* __restrict__ labels)
{
    __shared__ unsigned short smk[NL * 4 * 64];
    __shared__ unsigned short szf[NL * 64 * 64];   // [L][z][x], 24 KB

    const int tid = threadIdx.x;
    const int b = (int)blockIdx.x >> 6, y = (int)blockIdx.x & 63;
    const int x = tid & 63, seg = tid >> 6;

    // partial occupancy masks for z in [16*seg, 16*seg+16)
    unsigned m0 = 0, m1 = 0, m2 = 0;
    const int* lp = labels + b * VOL + seg * 16 * 4096 + y * 64 + x;
    #pragma unroll
    for (int zz = 0; zz < 16; ++zz) {
        int lab = lp[zz * 4096];
        m0 |= (lab == 0) ? (1u << zz) : 0u;
        m1 |= (lab == 1) ? (1u << zz) : 0u;
        m2 |= (lab == 2) ? (1u << zz) : 0u;
    }
    smk[(0 * 4 + seg) * 64 + x] = (unsigned short)m0;
    smk[(1 * 4 + seg) * 64 + x] = (unsigned short)m1;
    smk[(2 * 4 + seg) * 64 + x] = (unsigned short)m2;
    __syncthreads();

    // 192 threads: one (L, x) column each; fwd/bwd nearest-set-bit scan
    if (tid < 192) {
        int L = tid >> 6, xx = tid & 63;
        unsigned long long m =
              (unsigned long long)smk[(L * 4 + 0) * 64 + xx]
            | ((unsigned long long)smk[(L * 4 + 1) * 64 + xx] << 16)
            | ((unsigned long long)smk[(L * 4 + 2) * 64 + xx] << 32)
            | ((unsigned long long)smk[(L * 4 + 3) * 64 + xx] << 48);
        int dist[64];
        int d = 127;
        #pragma unroll
        for (int z = 0; z < 64; ++z) {
            d = ((m >> z) & 1ull) ? 0 : min(d + 1, 127);
            dist[z] = d;
        }
        d = 127;
        #pragma unroll
        for (int z = 63; z >= 0; --z) {
            d = ((m >> z) & 1ull) ? 0 : min(d + 1, 127);
            int dd = min(dist[z], d);
            szf[(L * 64 + z) * 64 + xx] =
                (unsigned short)((dd > 63) ? INF16 : dd * dd);
        }
    }
    __syncthreads();

    // coalesced copy-out of the FULL slab: NL*64*64 u16 = 6144 u32 words
    const unsigned* s32 = (const unsigned*)szf;
    #pragma unroll
    for (int e = 0; e < 24; ++e) {            // FIXED: was 6 (copied only 1/4)
        int w  = e * 256 + tid;               // 0..6143 = (L, z, xp)
        int L  = w >> 11, rem = w & 2047;
        int z  = rem >> 5, xp = rem & 31;
        g_zf32[(b * NL + L) * FW + z * 2048 + y * 32 + xp] = s32[w];
    }
}

// ---------------------------------------------------------------------------
// Windowed SIMD min-plus: rows (i0+m+8)*PITCH + lane, m = -8..11, d^2 as
// compile-time dup16 immediates. Returns 1 if any output > THR (inexact risk).
// ---------------------------------------------------------------------------
template<int PITCH>
__device__ __forceinline__ int win_minplus(const unsigned* __restrict__ s0,
                                           const unsigned* __restrict__ s1,
                                           const unsigned* __restrict__ s2,
                                           int lane, int i0, unsigned acc[NL][4])
{
    #pragma unroll
    for (int L = 0; L < NL; ++L)
        #pragma unroll
        for (int k = 0; k < 4; ++k) acc[L][k] = 0x7FFF7FFFu;

    #pragma unroll
    for (int m = -RWIN; m <= RWIN + 3; ++m) {
        const int row = (i0 + m + 8) * PITCH + lane;
        unsigned v0 = s0[row], v1 = s1[row], v2 = s2[row];
        #pragma unroll
        for (int k = 0; k < 4; ++k) {
            const int d = m - k;
            if (d < -RWIN || d > RWIN) continue;
            const unsigned q = (unsigned)(d * d) * 0x10001u;
            acc[0][k] = __viaddmin_s16x2(v0, q, acc[0][k]);
            acc[1][k] = __viaddmin_s16x2(v1, q, acc[1][k]);
            acc[2][k] = __viaddmin_s16x2(v2, q, acc[2][k]);
        }
    }
    unsigned mx = 0;
    #pragma unroll
    for (int L = 0; L < NL; ++L)
        #pragma unroll
        for (int k = 0; k < 4; ++k) mx = __vmaxu2(mx, acc[L][k]);
    return ((mx & 0xFFFFu) > THR) | ((mx >> 16) > THR);
}

// ---------------------------------------------------------------------------
// Kernel B: block = (b, z-plane t, y-half). 256 blocks x 256 threads.
// z-vals LOADED from g_zf32 (coalesced, L2-hot) instead of recomputed.
// ---------------------------------------------------------------------------
__global__ void __launch_bounds__(256, 2)
k_main(const float* __restrict__ x, const int* __restrict__ y,
       float* __restrict__ out)
{
    __shared__ unsigned sv[NL][48 * 33];   // z-vals rows y0-8..y0+39; reused as res
    __shared__ unsigned sw[NL][80 * 17];   // y-result transposed (x rows -8..71)
    __shared__ float    dtlut[THR + 1];
    __shared__ float    wsum[8];

    const int tid = threadIdx.x;
    const int bid = (int)blockIdx.x;
    const int b   = bid >> 7;
    const int t   = (bid & 127) >> 1;
    const int y0  = (bid & 1) * 32;

    if (tid <= THR) dtlut[tid] = fmaf(W_ANI, sqrtf((float)tid), 1.0f);

    // ---- entry prefetch, consumed immediately: weights s8 + packed labels
    const int gbase = b * VOL + t * 4096 + y0 * 64;
    float s8[8];
    unsigned labp = 0;
    #pragma unroll
    for (int e = 0; e < 8; ++e) {
        int v = e * 256 + tid;
        int lab  = y[gbase + v];
        float x1 = x[(b * NL + 1) * VOL + t * 4096 + y0 * 64 + v];
        float x2 = x[(b * NL + 2) * VOL + t * 4096 + y0 * 64 + v];
        s8[e] = ((lab == 1) ? (1.0f - x1) : x1)
              + ((lab == 2) ? (1.0f - x2) : x2);
        labp |= (unsigned)lab << (2 * e);
    }

    // ---- z-vals for rows y0-8 .. y0+39 from the precomputed field
    #pragma unroll
    for (int e = 0; e < 6; ++e) {
        int widx = e * 256 + tid;              // 0..1535
        int r = widx >> 5, xp = widx & 31;
        int ygl = y0 - 8 + r;
        bool valid = ((unsigned)ygl < 64u);
        #pragma unroll
        for (int L = 0; L < NL; ++L) {
            unsigned word = INFDUP;
            if (valid)
                word = g_zf32[(b * NL + L) * FW + t * 2048 + ygl * 32 + xp];
            sv[L][r * 33 + xp] = word;
        }
    }
    // sw guard rows (x = -8..-1, 64..71)
    for (int w = tid; w < NL * 16 * 17; w += 256) {
        int L = w / 272, rem = w - L * 272;
        int rr = rem / 17, c = rem - rr * 17;
        int row = (rr < 8) ? rr : (rr + 64);
        sw[L][row * 17 + c] = INFDUP;
    }
    __syncthreads();

    unsigned acc[NL][4];

    // ================= y-minplus (scan y, lines = x) =================
    const int cp = tid & 31;
    const int i0 = (tid >> 5) * 4;
    int bad = win_minplus<33>(sv[0], sv[1], sv[2], cp, i0, acc);
    const int fb1 = __syncthreads_or(bad);
    if (fb1) {
        // exact fallback from the global z-field (cold path)
        #pragma unroll
        for (int L = 0; L < NL; ++L)
            #pragma unroll
            for (int k = 0; k < 4; ++k) acc[L][k] = 0x7FFF7FFFu;
        for (int j = 0; j < 64; ++j) {
            #pragma unroll
            for (int L = 0; L < NL; ++L) {
                unsigned vj = g_zf32[(b * NL + L) * FW + t * 2048 + j * 32 + cp];
                #pragma unroll
                for (int k = 0; k < 4; ++k) {
                    int d = j - (y0 + i0 + k);
                    unsigned q = (unsigned)(d * d) * 0x10001u;
                    acc[L][k] = __viaddmin_s16x2(vj, q, acc[L][k]);
                }
            }
        }
    }
    // clamp + transposed write into sw
    #pragma unroll
    for (int L = 0; L < NL; ++L) {
        unsigned short* sw16 = (unsigned short*)sw[L];
        #pragma unroll
        for (int k = 0; k < 4; ++k) {
            unsigned a = __vminu2(acc[L][k], INFDUP);
            sw16[(2 * cp + 8) * 34 + (i0 + k)] = (unsigned short)(a & 0xFFFFu);
            sw16[(2 * cp + 9) * 34 + (i0 + k)] = (unsigned short)(a >> 16);
        }
    }
    __syncthreads();

    // ================= x-minplus (scan x, lines = y) =================
    const int cp2 = tid & 15;
    const int j0  = (tid >> 4) * 4;
    bad = win_minplus<17>(sw[0], sw[1], sw[2], cp2, j0, acc);
    const int fb2 = __syncthreads_or(bad);
    if (fb2) {
        #pragma unroll
        for (int L = 0; L < NL; ++L)
            #pragma unroll
            for (int k = 0; k < 4; ++k) acc[L][k] = 0x7FFF7FFFu;
        for (int j = 0; j < 64; ++j) {
            #pragma unroll
            for (int L = 0; L < NL; ++L) {
                unsigned vj = sw[L][(j + 8) * 17 + cp2];
                #pragma unroll
                for (int k = 0; k < 4; ++k) {
                    int d = j - (j0 + k);
                    unsigned q = (unsigned)(d * d) * 0x10001u;
                    acc[L][k] = __viaddmin_s16x2(vj, q, acc[L][k]);
                }
            }
        }
    }
    // result res16[ylocal*66 + x] (reuse sv)
    #pragma unroll
    for (int L = 0; L < NL; ++L) {
        unsigned short* res16 = (unsigned short*)sv[L];
        #pragma unroll
        for (int k = 0; k < 4; ++k) {
            res16[(2 * cp2)     * 66 + (j0 + k)] = (unsigned short)(acc[L][k] & 0xFFFFu);
            res16[(2 * cp2 + 1) * 66 + (j0 + k)] = (unsigned short)(acc[L][k] >> 16);
        }
    }
    __syncthreads();

    // ---- fused reduce: dt via LUT when both windowed passes were exact
    const unsigned short* r0 = (const unsigned short*)sv[0];
    const unsigned short* r1 = (const unsigned short*)sv[1];
    const unsigned short* r2 = (const unsigned short*)sv[2];
    const bool exact = !(fb1 | fb2);
    float local = 0.0f;
    #pragma unroll
    for (int e = 0; e < 8; ++e) {
        int v   = e * 256 + tid;
        int lab = (labp >> (2 * e)) & 3;
        int yy = v >> 6, xx = v & 63;
        int n0 = r0[yy * 66 + xx];
        int n1 = r1[yy * 66 + xx];
        int n2 = r2[yy * 66 + xx];
        int m = min(lab == 0 ? 0x7FFF : n0,
                min(lab == 1 ? 0x7FFF : n1,
                    lab == 2 ? 0x7FFF : n2));
        float dt = exact ? dtlut[m]
                         : fmaf(W_ANI, sqrtf((float)m), 1.0f);
        local += s8[e] * dt;
    }

    #pragma unroll
    for (int o = 16; o; o >>= 1)
        local += __shfl_xor_sync(0xFFFFFFFFu, local, o);
    if ((tid & 31) == 0) wsum[tid >> 5] = local;
    __syncthreads();

    if (tid == 0) {
        float s = 0.0f;
        #pragma unroll
        for (int i = 0; i < 8; ++i) s += wsum[i];
        atomicAdd(&g_acc, (double)s);
        __threadfence();
        unsigned old = atomicAdd(&g_done, 1u);
        if (old == gridDim.x - 1) {            // last block: finalize + reset
            double tot = atomicAdd(&g_acc, 0.0);
            out[0] = (float)(tot / (double)(NB * 2 * VOL) + 1e-5);
            g_acc  = 0.0;
            g_done = 0u;
            __threadfence();
        }
    }
}

// ---------------------------------------------------------------------------
extern "C" void kernel_launch(void* const* d_in, const int* in_sizes, int n_in,
                              void* d_out, int out_size)
{
    const float* x = (const float*)d_in[0];   // (2,3,64,64,64) f32
    const int*   y = (const int*)  d_in[1];   // (2,1,64,64,64) i32
    float* out = (float*)d_out;

    k_zfield<<<NB * 64, 256>>>(y);
    k_main  <<<NB * 128, 256>>>(x, y, out);
}